// round 9
// baseline (speedup 1.0000x reference)
#include <cuda_runtime.h>
#include <math.h>

#define Bsz 256
#define Tsz 128
#define Fsz 128
#define Hsz 512
#define BT  (Bsz * Tsz)          // 32768
#define KC  768                  // c_c(128) + h_dec(512) + m(128)
#define N4H 2048                 // 4*H, gate-interleaved
#define NBLK 128                 // persistent grid size

typedef unsigned long long ull;

// ----- device scratch (allocation-free rule: __device__ globals) -----
__device__ __align__(16) float g_h[Bsz * Hsz];
__device__ __align__(16) float g_c[Bsz * Hsz];
__device__ __align__(16) float g_xvec[Bsz * KC];
__device__ __align__(16) float g_xhist[Bsz * Fsz];
__device__ __align__(16) float g_gamma_h[(size_t)BT * Hsz];   // 64 MB
__device__ __align__(16) float g_alpha[BT * Fsz];
__device__ float g_losspart[Tsz * 128];
__device__ float g_maskpart[Tsz * 128];
__device__ __align__(16) float g_tdhT[Fsz * Hsz];
__device__ __align__(16) float g_histT[Hsz * Fsz];
__device__ __align__(16) float g_featMT[Fsz * Fsz];
__device__ __align__(16) float g_wcT[2 * Fsz * Fsz];
__device__ __align__(16) float g_WcombT[KC * N4H];
__device__ __align__(16) float g_bcomb[N4H];
__device__ __align__(16) float g_p1part[32 * 4 * 1024];             // P1 split-K partials
__device__ int g_cnt1[32];
__device__ volatile int g_x1flag[32];    // P1 tile-done flags (monotone per step)

// flag-array grid barrier
__device__ volatile int g_arrive[NBLK];
__device__ volatile int g_release;

__device__ __forceinline__ float fsigmoid(float v) {
    return __fdividef(1.f, 1.f + __expf(-v));
}
__device__ __forceinline__ float tanhap(float x) {
    float r;
    asm("tanh.approx.f32 %0, %1;" : "=f"(r) : "f"(x));
    return r;
}
__device__ __forceinline__ float sigap(float v) {
    return 0.5f * tanhap(0.5f * v) + 0.5f;
}

// ----------------------------------------------------------------------
__global__ void prep_weights(const float* __restrict__ td_h_W,
                             const float* __restrict__ hist_W,
                             const float* __restrict__ feat_W,
                             const float* __restrict__ wc_W,
                             const float* __restrict__ W_ih,
                             const float* __restrict__ W_hh,
                             const float* __restrict__ b_ih,
                             const float* __restrict__ b_hh) {
    int stride = gridDim.x * blockDim.x;
    int tid = blockIdx.x * blockDim.x + threadIdx.x;
    for (int i = tid; i < Fsz * Hsz; i += stride) {
        int k = i / Hsz, n = i % Hsz;
        g_tdhT[i] = td_h_W[n * Fsz + k];
    }
    for (int i = tid; i < Hsz * Fsz; i += stride) {
        int k = i / Fsz, f = i % Fsz;
        g_histT[i] = hist_W[f * Hsz + k];
    }
    for (int i = tid; i < Fsz * Fsz; i += stride) {
        int j = i / Fsz, f = i % Fsz;
        g_featMT[i] = (j == f) ? 0.f : feat_W[f * Fsz + j];
    }
    for (int i = tid; i < 2 * Fsz * Fsz; i += stride) {
        int k = i / Fsz, n = i % Fsz;
        g_wcT[i] = wc_W[n * 2 * Fsz + k];
    }
    for (int i = tid; i < KC * N4H; i += stride) {
        int k = i / N4H, n = i % N4H;
        int j = n >> 2, g = n & 3;
        int row = g * Hsz + j;
        float v;
        if (k < Fsz)            v = W_ih[row * (2 * Fsz) + k];
        else if (k < Fsz + Hsz) v = W_hh[row * Hsz + (k - Fsz)];
        else                    v = W_ih[row * (2 * Fsz) + Fsz + (k - Fsz - Hsz)];
        g_WcombT[i] = v;
    }
    for (int i = tid; i < N4H; i += stride) {
        int j = i >> 2, g = i & 3;
        g_bcomb[i] = b_ih[g * Hsz + j] + b_hh[g * Hsz + j];
    }
}

// ----------------------------------------------------------------------
// gamma_h GEMM: M=BT, N=512, K=128
// ----------------------------------------------------------------------
__global__ void gammah_gemm(const float* __restrict__ d,
                            const float* __restrict__ td_h_b) {
    __shared__ float sA[64][33];
    __shared__ float sB[32][64];
    int m0 = blockIdx.x * 64;
    int n0 = blockIdx.y * 64;
    int tid = threadIdx.x;
    int tx = tid & 15, ty = tid >> 4;
    float acc[4][4] = {};
    for (int kk = 0; kk < Fsz; kk += 32) {
        for (int i = tid; i < 64 * 32; i += 256) {
            int r = i >> 5, k = i & 31;
            sA[r][k] = d[(size_t)(m0 + r) * Fsz + kk + k];
        }
        for (int i = tid; i < 32 * 64; i += 256) {
            int k = i >> 6, n = i & 63;
            sB[k][n] = g_tdhT[(kk + k) * Hsz + n0 + n];
        }
        __syncthreads();
#pragma unroll
        for (int k = 0; k < 32; k++) {
            float a[4], b[4];
#pragma unroll
            for (int i = 0; i < 4; i++) a[i] = sA[ty + i * 16][k];
#pragma unroll
            for (int j = 0; j < 4; j++) b[j] = sB[k][tx + j * 16];
#pragma unroll
            for (int i = 0; i < 4; i++)
#pragma unroll
                for (int j = 0; j < 4; j++) acc[i][j] += a[i] * b[j];
        }
        __syncthreads();
    }
#pragma unroll
    for (int i = 0; i < 4; i++)
#pragma unroll
        for (int j = 0; j < 4; j++) {
            int n = n0 + tx + j * 16;
            int row = m0 + ty + i * 16;
            g_gamma_h[(size_t)row * Hsz + n] = __expf(-fmaxf(acc[i][j] + td_h_b[n], 0.f));
        }
}

// ----------------------------------------------------------------------
// alpha GEMM M=BT, N=128, K=256 — gamma_x computed inline in the A-load
// ----------------------------------------------------------------------
__global__ void alpha_gemm(const float* __restrict__ d,
                           const float* __restrict__ m,
                           const float* __restrict__ td_x_W,
                           const float* __restrict__ td_x_b,
                           const float* __restrict__ wc_b) {
    __shared__ float sA[64][33];
    __shared__ float sB[32][64];
    int m0 = blockIdx.x * 64;
    int n0 = blockIdx.y * 64;
    int tid = threadIdx.x;
    int tx = tid & 15, ty = tid >> 4;
    float acc[4][4] = {};
    for (int kk = 0; kk < 2 * Fsz; kk += 32) {
        for (int i = tid; i < 64 * 32; i += 256) {
            int r = i >> 5, k = i & 31;
            int kg = kk + k;
            float v;
            if (kg < Fsz) {
                float dv = d[(size_t)(m0 + r) * Fsz + kg];
                float u = dv * td_x_W[kg * Fsz + kg] + td_x_b[kg];
                v = __expf(-fmaxf(u, 0.f));
            } else {
                v = m[(size_t)(m0 + r) * Fsz + (kg - Fsz)];
            }
            sA[r][k] = v;
        }
        for (int i = tid; i < 32 * 64; i += 256) {
            int k = i >> 6, n = i & 63;
            sB[k][n] = g_wcT[(kk + k) * Fsz + n0 + n];
        }
        __syncthreads();
#pragma unroll
        for (int k = 0; k < 32; k++) {
            float a[4], b[4];
#pragma unroll
            for (int i = 0; i < 4; i++) a[i] = sA[ty + i * 16][k];
#pragma unroll
            for (int j = 0; j < 4; j++) b[j] = sB[k][tx + j * 16];
#pragma unroll
            for (int i = 0; i < 4; i++)
#pragma unroll
                for (int j = 0; j < 4; j++) acc[i][j] += a[i] * b[j];
        }
        __syncthreads();
    }
#pragma unroll
    for (int i = 0; i < 4; i++)
#pragma unroll
        for (int j = 0; j < 4; j++) {
            int n = n0 + tx + j * 16;
            int row = m0 + ty + i * 16;
            float v = acc[i][j] + wc_b[n];
            g_alpha[row * Fsz + n] = fsigmoid(v);
        }
}

// ======================================================================
#define FMA2(acc, a2, b2) \
    asm("fma.rn.f32x2 %0, %1, %2, %0;" : "+l"(acc) : "l"(a2), "l"(b2))
#define DUP32(d, s) \
    asm("mov.b64 %0, {%1, %1};" : "=l"(d) : "r"(s))
#define UNPACK2(lo, hi, in) \
    asm("mov.b64 {%0, %1}, %2;" : "=f"(lo), "=f"(hi) : "l"(in))

// flag-array barrier: one STG per block, block 0 gathers, no atomic contention
__device__ __forceinline__ void grid_sync(int& gen) {
    gen++;
    __threadfence();
    __syncthreads();
    if (blockIdx.x == 0) {
        int tid = threadIdx.x;
        if (tid > 0 && tid < NBLK) {
            while (g_arrive[tid] - gen < 0) { }
        }
        __syncthreads();
        if (tid == 0) g_release = gen;
    } else {
        if (threadIdx.x == 0) {
            g_arrive[blockIdx.x] = gen;
            while (g_release - gen < 0) { }
        }
    }
    __syncthreads();
    __threadfence();
}

__global__ void __launch_bounds__(256, 1)
rits_persistent(const float* __restrict__ x,
                const float* __restrict__ m,
                const float* __restrict__ target_x,
                const float* __restrict__ target_mask,
                const float* __restrict__ hist_b,
                const float* __restrict__ feat_b,
                float* __restrict__ out) {
    // P4: sAd ull[64][33] (16896B) + s4B float[32][68] (8704B) = 25600B
    // P1 aliases: p1A float 32x33, p1B float 32x34
    // P2 aliases: s2A 16x132, s2B 128x17, sred, sred2
    __shared__ __align__(16) unsigned char smem_raw[25600];
    __shared__ int s_last;
    ull*   sAd = reinterpret_cast<ull*>(smem_raw);                  // [64][33] ull
    float* s4B = reinterpret_cast<float*>(smem_raw + 16896);        // [32][68]
    float* p1A = reinterpret_cast<float*>(smem_raw);                // [32][33]
    float* p1B = p1A + 1056;                                        // [32][34]
    float* s2A = reinterpret_cast<float*>(smem_raw);                // [16][132]
    float* s2B = s2A + 2112;                                        // [128][17]
    float* sred  = s2B + 2176;
    float* sred2 = sred + 8;

    const int tid = threadIdx.x;
    const int bid = blockIdx.x;

    int gen = g_release;

    // init state (+ reset P1 flags each replay)
    for (int i = bid * 256 + tid; i < Bsz * Hsz; i += NBLK * 256) {
        g_h[i] = 0.f; g_c[i] = 0.f;
    }
    if (bid == 0 && tid < 32) g_x1flag[tid] = 0;
    grid_sync(gen);

    const int tx = tid & 15, ty = tid >> 4;

    // P1 decode: 32 tiles (8 row x 4 col of 32x32) x 4-way K-split
    const int tile1 = bid >> 2, ks1 = bid & 3;
    const int r0_1 = (tile1 >> 2) * 32, n0_1 = (tile1 & 3) * 32;
    const bool wr_xvec = ((tile1 & 3) == 0);

    // P2 decode: 128 tiles of 16x16; needs x_hist tiles (rb, 0..3)
    const int r0_2 = (bid >> 3) * 16, n0_2 = (bid & 7) * 16;
    const int rb = bid >> 4;

    // P4 decode: 128 tiles of 64 rows x 64 gate-cols, full K=768
    const int b0B = (bid >> 5) * 64;
    const int n0_4 = (bid & 31) * 64;

#pragma unroll 1
    for (int t = 0; t < Tsz; t++) {
        // ================= P1: x_hist GEMM (decay folded into A-load) =================
        {
            ull acc0 = 0ull, acc1 = 0ull;
#pragma unroll 1
            for (int kb = 0; kb < 4; kb++) {
                const int k0 = ks1 * 128 + kb * 32;
                __syncthreads();
#pragma unroll
                for (int q = 0; q < 4; q++) {
                    int i = tid + q * 256;
                    int r = i >> 5, k = i & 31;
                    float hv = g_h[(r0_1 + r) * Hsz + k0 + k] *
                               g_gamma_h[((size_t)(r0_1 + r) * Tsz + t) * Hsz + k0 + k];
                    p1A[r * 33 + k] = hv;
                    if (wr_xvec) g_xvec[(r0_1 + r) * KC + Fsz + k0 + k] = hv;
                }
#pragma unroll
                for (int q = 0; q < 4; q++) {
                    int i = tid + q * 256;
                    int k = i >> 5, n = i & 31;
                    p1B[k * 34 + n] = g_histT[(k0 + k) * Fsz + n0_1 + n];
                }
                __syncthreads();
#pragma unroll
                for (int k = 0; k < 32; k++) {
                    ull b2 = *reinterpret_cast<ull*>(&p1B[k * 34 + tx * 2]);
                    ull a0d, a1d;
                    DUP32(a0d, __float_as_uint(p1A[(ty * 2) * 33 + k]));
                    DUP32(a1d, __float_as_uint(p1A[(ty * 2 + 1) * 33 + k]));
                    FMA2(acc0, a0d, b2);
                    FMA2(acc1, a1d, b2);
                }
            }
            size_t pb = (size_t)(tile1 * 4 + ks1) * 1024;
            *reinterpret_cast<ull*>(&g_p1part[pb + (ty * 2) * 32 + tx * 2]) = acc0;
            *reinterpret_cast<ull*>(&g_p1part[pb + (ty * 2 + 1) * 32 + tx * 2]) = acc1;
            __threadfence();
            __syncthreads();
            if (tid == 0) {
                int old = atomicAdd(&g_cnt1[tile1], 1);
                s_last = (old == 3);
            }
            __syncthreads();
            if (s_last) {
                __threadfence();
                size_t tb = (size_t)tile1 * 4 * 1024;
                for (int idx = tid; idx < 1024; idx += 256) {
                    int r = idx >> 5, n = idx & 31;
                    float v = ((g_p1part[tb + idx] + g_p1part[tb + 1024 + idx]) +
                               (g_p1part[tb + 2048 + idx] + g_p1part[tb + 3072 + idx])) +
                              hist_b[n0_1 + n];
                    g_xhist[(r0_1 + r) * Fsz + n0_1 + n] = v;
                }
                __threadfence();
                __syncthreads();
                if (tid == 0) {
                    g_cnt1[tile1] = 0;
                    g_x1flag[tile1] = t + 1;   // publish
                }
            }
        }

        // ================= P2: z_h GEMM + elementwise epilogue + loss =================
        {
            // wait for the 4 x_hist tiles covering rows [rb*32, rb*32+32)
            if (tid < 4) {
                while (g_x1flag[rb * 4 + tid] - (t + 1) < 0) { }
            }
            __syncthreads();
            __threadfence();   // acquire

#pragma unroll
            for (int q = 0; q < 8; q++) {
                int i = tid + q * 256;
                int r = i >> 7, k = i & 127;
                size_t base = ((size_t)(r0_2 + r) * Tsz + t) * Fsz + k;
                float mv = m[base], xv = x[base];
                float xh = g_xhist[(r0_2 + r) * Fsz + k];
                s2A[r * 132 + k] = mv * xv + (1.f - mv) * xh;
            }
#pragma unroll
            for (int q = 0; q < 8; q++) {
                int i = tid + q * 256;
                int k = i >> 4, n = i & 15;
                s2B[k * 17 + n] = g_featMT[k * Fsz + n0_2 + n];
            }
            __syncthreads();
            int rl = tid >> 4, nl = tid & 15;
            float z0 = 0.f, z1 = 0.f, z2 = 0.f, z3 = 0.f;
#pragma unroll 8
            for (int k = 0; k < 128; k += 4) {
                z0 += s2A[rl * 132 + k]     * s2B[(k)     * 17 + nl];
                z1 += s2A[rl * 132 + k + 1] * s2B[(k + 1) * 17 + nl];
                z2 += s2A[rl * 132 + k + 2] * s2B[(k + 2) * 17 + nl];
                z3 += s2A[rl * 132 + k + 3] * s2B[(k + 3) * 17 + nl];
            }
            int r = r0_2 + rl, n = n0_2 + nl;
            size_t base = ((size_t)r * Tsz + t) * Fsz + n;
            float z = ((z0 + z1) + (z2 + z3)) + feat_b[n];
            float xh = g_xhist[r * Fsz + n];
            float a = g_alpha[base];
            float mv = m[base], xv = x[base];
            float ch = a * z + (1.f - a) * xh;
            float cc = mv * xv + (1.f - mv) * ch;
            g_xvec[r * KC + n] = cc;
            g_xvec[r * KC + (Fsz + Hsz) + n] = mv;
            out[base] = cc;
            float ev = target_mask[base];
            float tg = target_x[base];
            float d1 = xh - tg, d2 = z - tg, d3 = ch - tg;
            float lp = ev * (d1 * d1 + d2 * d2 + d3 * d3);
            float es = ev;
            for (int o = 16; o; o >>= 1) {
                lp += __shfl_down_sync(0xffffffffu, lp, o);
                es += __shfl_down_sync(0xffffffffu, es, o);
            }
            if ((tid & 31) == 0) { sred[tid >> 5] = lp; sred2[tid >> 5] = es; }
            __syncthreads();
            if (tid == 0) {
                float tot = 0.f, tot2 = 0.f;
                for (int i = 0; i < 8; i++) { tot += sred[i]; tot2 += sred2[i]; }
                g_losspart[t * 128 + bid] = tot;
                g_maskpart[t * 128 + bid] = tot2;
            }
        }
        grid_sync(gen);

        // ================= P4: gate GEMM 64x64x768 (no split-K) + LSTM epilogue =================
        {
            ull acc[4][2];
#pragma unroll
            for (int i = 0; i < 4; i++) { acc[i][0] = 0ull; acc[i][1] = 0ull; }

            // prefetch chunk 0
            float4 pa[2], pb[2];
#pragma unroll
            for (int q = 0; q < 2; q++) {
                int i = tid + q * 256;
                int mm = i >> 3, kq = i & 7;
                pa[q] = *reinterpret_cast<const float4*>(
                    &g_xvec[(b0B + mm) * KC + kq * 4]);
            }
#pragma unroll
            for (int q = 0; q < 2; q++) {
                int i = tid + q * 256;
                int kk = i >> 4, nq = i & 15;
                pb[q] = *reinterpret_cast<const float4*>(
                    &g_WcombT[(size_t)kk * N4H + n0_4 + nq * 4]);
            }

#pragma unroll 1
            for (int kb = 0; kb < 24; kb++) {
                __syncthreads();
#pragma unroll
                for (int q = 0; q < 2; q++) {
                    int i = tid + q * 256;
                    int mm = i >> 3, kq = i & 7;
                    ull* dst = &sAd[mm * 33 + kq * 4];
                    ull d0, d1, d2, d3;
                    DUP32(d0, __float_as_uint(pa[q].x));
                    DUP32(d1, __float_as_uint(pa[q].y));
                    DUP32(d2, __float_as_uint(pa[q].z));
                    DUP32(d3, __float_as_uint(pa[q].w));
                    dst[0] = d0; dst[1] = d1; dst[2] = d2; dst[3] = d3;
                }
#pragma unroll
                for (int q = 0; q < 2; q++) {
                    int i = tid + q * 256;
                    int kk = i >> 4, nq = i & 15;
                    *reinterpret_cast<float4*>(&s4B[kk * 68 + nq * 4]) = pb[q];
                }
                __syncthreads();
                if (kb < 23) {
                    const int k0n = (kb + 1) * 32;
#pragma unroll
                    for (int q = 0; q < 2; q++) {
                        int i = tid + q * 256;
                        int mm = i >> 3, kq = i & 7;
                        pa[q] = *reinterpret_cast<const float4*>(
                            &g_xvec[(b0B + mm) * KC + k0n + kq * 4]);
                    }
#pragma unroll
                    for (int q = 0; q < 2; q++) {
                        int i = tid + q * 256;
                        int kk = i >> 4, nq = i & 15;
                        pb[q] = *reinterpret_cast<const float4*>(
                            &g_WcombT[(size_t)(k0n + kk) * N4H + n0_4 + nq * 4]);
                    }
                }
#pragma unroll 8
                for (int k = 0; k < 32; k++) {
                    ulonglong2 bb = *reinterpret_cast<const ulonglong2*>(
                        &s4B[k * 68 + tx * 4]);
#pragma unroll
                    for (int r2 = 0; r2 < 4; r2++) {
                        ull ad = sAd[(ty * 4 + r2) * 33 + k];
                        FMA2(acc[r2][0], ad, bb.x);
                        FMA2(acc[r2][1], ad, bb.y);
                    }
                }
            }

            // LSTM epilogue — in registers, evenly distributed across all blocks
            float4 bc = *reinterpret_cast<const float4*>(&g_bcomb[n0_4 + tx * 4]);
            int j = (n0_4 >> 2) + tx;
#pragma unroll
            for (int r2 = 0; r2 < 4; r2++) {
                int b = b0B + ty * 4 + r2;
                float gi, gf, gg, gO;
                UNPACK2(gi, gf, acc[r2][0]);
                UNPACK2(gg, gO, acc[r2][1]);
                gi += bc.x; gf += bc.y; gg += bc.z; gO += bc.w;
                float si = sigap(gi);
                float sf = sigap(gf);
                float so = sigap(gO);
                float tg = tanhap(gg);
                float cn = sf * g_c[b * Hsz + j] + si * tg;
                g_c[b * Hsz + j] = cn;
                g_h[b * Hsz + j] = so * tanhap(cn);
            }
        }
        grid_sync(gen);
    }
}

// ----------------------------------------------------------------------
__global__ void loss_final(float* __restrict__ out, int out_size) {
    __shared__ float s[128];
    int t = threadIdx.x;
    float v = 0.f, mv = 0.f;
    for (int p = 0; p < 128; p++) {
        v += g_losspart[t * 128 + p];
        mv += g_maskpart[t * 128 + p];
    }
    s[t] = v / (mv + 1e-8f);
    __syncthreads();
    if (t == 0) {
        float tot = 0.f;
        for (int i = 0; i < 128; i++) tot += s[i];
        out[out_size - 1] = tot / (float)Tsz;
    }
}

// ----------------------------------------------------------------------
extern "C" void kernel_launch(void* const* d_in, const int* in_sizes, int n_in,
                              void* d_out, int out_size) {
    const float* x           = (const float*)d_in[0];
    const float* m           = (const float*)d_in[1];
    const float* d           = (const float*)d_in[2];
    const float* target_x    = (const float*)d_in[3];
    const float* target_mask = (const float*)d_in[4];
    const float* td_h_W      = (const float*)d_in[5];
    const float* td_h_b      = (const float*)d_in[6];
    const float* td_x_W      = (const float*)d_in[7];
    const float* td_x_b      = (const float*)d_in[8];
    const float* hist_W      = (const float*)d_in[9];
    const float* hist_b      = (const float*)d_in[10];
    const float* feat_W      = (const float*)d_in[11];
    const float* feat_b      = (const float*)d_in[12];
    const float* wc_W        = (const float*)d_in[13];
    const float* wc_b        = (const float*)d_in[14];
    const float* W_ih        = (const float*)d_in[15];
    const float* W_hh        = (const float*)d_in[16];
    const float* b_ih        = (const float*)d_in[17];
    const float* b_hh        = (const float*)d_in[18];
    float* out = (float*)d_out;

    prep_weights<<<512, 256>>>(td_h_W, hist_W, feat_W, wc_W, W_ih, W_hh, b_ih, b_hh);
    gammah_gemm<<<dim3(BT / 64, Hsz / 64), 256>>>(d, td_h_b);
    alpha_gemm<<<dim3(BT / 64, Fsz / 64), 256>>>(d, m, td_x_W, td_x_b, wc_b);

    rits_persistent<<<NBLK, 256>>>(x, m, target_x, target_mask, hist_b, feat_b, out);

    loss_final<<<1, 128>>>(out, out_size);
}

// round 10
// speedup vs baseline: 1.0293x; 1.0293x over previous
#include <cuda_runtime.h>
#include <math.h>

#define Bsz 256
#define Tsz 128
#define Fsz 128
#define Hsz 512
#define BT  (Bsz * Tsz)          // 32768
#define KC  768                  // c_c(128) + h_dec(512) + m(128)
#define N4H 2048                 // 4*H, gate-interleaved
#define NBLK 128                 // persistent grid size
#define NTHR 512

typedef unsigned long long ull;

// ----- device scratch (allocation-free rule: __device__ globals) -----
__device__ __align__(16) float g_h[Bsz * Hsz];
__device__ __align__(16) float g_c[Bsz * Hsz];
__device__ __align__(16) float g_xvec[Bsz * KC];
__device__ __align__(16) float g_xhist[Bsz * Fsz];
__device__ __align__(16) float g_gamma_h[(size_t)BT * Hsz];   // 64 MB
__device__ __align__(16) float g_alpha[BT * Fsz];
__device__ float g_losspart[Tsz * 128];
__device__ float g_maskpart[Tsz * 128];
__device__ __align__(16) float g_tdhT[Fsz * Hsz];
__device__ __align__(16) float g_histT[Hsz * Fsz];
__device__ __align__(16) float g_featMT[Fsz * Fsz];
__device__ __align__(16) float g_wcT[2 * Fsz * Fsz];
__device__ __align__(16) float g_WcombT[KC * N4H];
__device__ __align__(16) float g_bcomb[N4H];
__device__ __align__(16) float g_part[(size_t)32 * 4 * 128 * 128];  // P4 split-K partials
__device__ __align__(16) float g_p1part[32 * 4 * 1024];             // P1 split-K partials
__device__ int g_cnt1[32];
__device__ int g_tilecnt[32];            // monotone within a replay
__device__ volatile int g_x1flag[32];    // P1 tile-done flags (monotone per step)

// flag-array grid barrier
__device__ volatile int g_arrive[NBLK];
__device__ volatile int g_release;

__device__ __forceinline__ float fsigmoid(float v) {
    return __fdividef(1.f, 1.f + __expf(-v));
}
__device__ __forceinline__ float tanhap(float x) {
    float r;
    asm("tanh.approx.f32 %0, %1;" : "=f"(r) : "f"(x));
    return r;
}
__device__ __forceinline__ float sigap(float v) {
    return 0.5f * tanhap(0.5f * v) + 0.5f;
}

// ----------------------------------------------------------------------
__global__ void prep_weights(const float* __restrict__ td_h_W,
                             const float* __restrict__ hist_W,
                             const float* __restrict__ feat_W,
                             const float* __restrict__ wc_W,
                             const float* __restrict__ W_ih,
                             const float* __restrict__ W_hh,
                             const float* __restrict__ b_ih,
                             const float* __restrict__ b_hh) {
    int stride = gridDim.x * blockDim.x;
    int tid = blockIdx.x * blockDim.x + threadIdx.x;
    for (int i = tid; i < Fsz * Hsz; i += stride) {
        int k = i / Hsz, n = i % Hsz;
        g_tdhT[i] = td_h_W[n * Fsz + k];
    }
    for (int i = tid; i < Hsz * Fsz; i += stride) {
        int k = i / Fsz, f = i % Fsz;
        g_histT[i] = hist_W[f * Hsz + k];
    }
    for (int i = tid; i < Fsz * Fsz; i += stride) {
        int j = i / Fsz, f = i % Fsz;
        g_featMT[i] = (j == f) ? 0.f : feat_W[f * Fsz + j];
    }
    for (int i = tid; i < 2 * Fsz * Fsz; i += stride) {
        int k = i / Fsz, n = i % Fsz;
        g_wcT[i] = wc_W[n * 2 * Fsz + k];
    }
    for (int i = tid; i < KC * N4H; i += stride) {
        int k = i / N4H, n = i % N4H;
        int j = n >> 2, g = n & 3;
        int row = g * Hsz + j;
        float v;
        if (k < Fsz)            v = W_ih[row * (2 * Fsz) + k];
        else if (k < Fsz + Hsz) v = W_hh[row * Hsz + (k - Fsz)];
        else                    v = W_ih[row * (2 * Fsz) + Fsz + (k - Fsz - Hsz)];
        g_WcombT[i] = v;
    }
    for (int i = tid; i < N4H; i += stride) {
        int j = i >> 2, g = i & 3;
        g_bcomb[i] = b_ih[g * Hsz + j] + b_hh[g * Hsz + j];
    }
}

// ----------------------------------------------------------------------
__global__ void gammah_gemm(const float* __restrict__ d,
                            const float* __restrict__ td_h_b) {
    __shared__ float sA[64][33];
    __shared__ float sB[32][64];
    int m0 = blockIdx.x * 64;
    int n0 = blockIdx.y * 64;
    int tid = threadIdx.x;
    int tx = tid & 15, ty = tid >> 4;
    float acc[4][4] = {};
    for (int kk = 0; kk < Fsz; kk += 32) {
        for (int i = tid; i < 64 * 32; i += 256) {
            int r = i >> 5, k = i & 31;
            sA[r][k] = d[(size_t)(m0 + r) * Fsz + kk + k];
        }
        for (int i = tid; i < 32 * 64; i += 256) {
            int k = i >> 6, n = i & 63;
            sB[k][n] = g_tdhT[(kk + k) * Hsz + n0 + n];
        }
        __syncthreads();
#pragma unroll
        for (int k = 0; k < 32; k++) {
            float a[4], b[4];
#pragma unroll
            for (int i = 0; i < 4; i++) a[i] = sA[ty + i * 16][k];
#pragma unroll
            for (int j = 0; j < 4; j++) b[j] = sB[k][tx + j * 16];
#pragma unroll
            for (int i = 0; i < 4; i++)
#pragma unroll
                for (int j = 0; j < 4; j++) acc[i][j] += a[i] * b[j];
        }
        __syncthreads();
    }
#pragma unroll
    for (int i = 0; i < 4; i++)
#pragma unroll
        for (int j = 0; j < 4; j++) {
            int n = n0 + tx + j * 16;
            int row = m0 + ty + i * 16;
            g_gamma_h[(size_t)row * Hsz + n] = __expf(-fmaxf(acc[i][j] + td_h_b[n], 0.f));
        }
}

// ----------------------------------------------------------------------
__global__ void alpha_gemm(const float* __restrict__ d,
                           const float* __restrict__ m,
                           const float* __restrict__ td_x_W,
                           const float* __restrict__ td_x_b,
                           const float* __restrict__ wc_b) {
    __shared__ float sA[64][33];
    __shared__ float sB[32][64];
    int m0 = blockIdx.x * 64;
    int n0 = blockIdx.y * 64;
    int tid = threadIdx.x;
    int tx = tid & 15, ty = tid >> 4;
    float acc[4][4] = {};
    for (int kk = 0; kk < 2 * Fsz; kk += 32) {
        for (int i = tid; i < 64 * 32; i += 256) {
            int r = i >> 5, k = i & 31;
            int kg = kk + k;
            float v;
            if (kg < Fsz) {
                float dv = d[(size_t)(m0 + r) * Fsz + kg];
                float u = dv * td_x_W[kg * Fsz + kg] + td_x_b[kg];
                v = __expf(-fmaxf(u, 0.f));
            } else {
                v = m[(size_t)(m0 + r) * Fsz + (kg - Fsz)];
            }
            sA[r][k] = v;
        }
        for (int i = tid; i < 32 * 64; i += 256) {
            int k = i >> 6, n = i & 63;
            sB[k][n] = g_wcT[(kk + k) * Fsz + n0 + n];
        }
        __syncthreads();
#pragma unroll
        for (int k = 0; k < 32; k++) {
            float a[4], b[4];
#pragma unroll
            for (int i = 0; i < 4; i++) a[i] = sA[ty + i * 16][k];
#pragma unroll
            for (int j = 0; j < 4; j++) b[j] = sB[k][tx + j * 16];
#pragma unroll
            for (int i = 0; i < 4; i++)
#pragma unroll
                for (int j = 0; j < 4; j++) acc[i][j] += a[i] * b[j];
        }
        __syncthreads();
    }
#pragma unroll
    for (int i = 0; i < 4; i++)
#pragma unroll
        for (int j = 0; j < 4; j++) {
            int n = n0 + tx + j * 16;
            int row = m0 + ty + i * 16;
            float v = acc[i][j] + wc_b[n];
            g_alpha[row * Fsz + n] = fsigmoid(v);
        }
}

// ======================================================================
#define FMA2(acc, a2, b2) \
    asm("fma.rn.f32x2 %0, %1, %2, %0;" : "+l"(acc) : "l"(a2), "l"(b2))
#define DUP32(d, s) \
    asm("mov.b64 %0, {%1, %1};" : "=l"(d) : "r"(s))
#define UNPACK2(lo, hi, in) \
    asm("mov.b64 {%0, %1}, %2;" : "=f"(lo), "=f"(hi) : "l"(in))

// flag-array barrier: one STG per block, block 0 gathers, no atomic contention
__device__ __forceinline__ void grid_sync(int& gen) {
    gen++;
    __threadfence();
    __syncthreads();
    if (blockIdx.x == 0) {
        int tid = threadIdx.x;
        if (tid > 0 && tid < NBLK) {
            while (g_arrive[tid] - gen < 0) { }
        }
        __syncthreads();
        if (tid == 0) g_release = gen;
    } else {
        if (threadIdx.x == 0) {
            g_arrive[blockIdx.x] = gen;
            while (g_release - gen < 0) { }
        }
    }
    __syncthreads();
    __threadfence();
}

__global__ void __launch_bounds__(NTHR, 1)
rits_persistent(const float* __restrict__ x,
                const float* __restrict__ m,
                const float* __restrict__ target_x,
                const float* __restrict__ target_mask,
                const float* __restrict__ hist_b,
                const float* __restrict__ feat_b,
                float* __restrict__ out) {
    // 8960 floats = 35.8KB
    // P4: sA float[128][36] (4608) + sB4 float[32][132] (4224) = 8832
    // P1: p1A [32][136] (4352) + p1B [128][36] (4608) = 8960
    // P2: s2A [16][132] (2112) + s2B [128][20] (2560) + sred(16) + sred2(16)
    __shared__ __align__(16) float smem[8960];
    __shared__ int s_last;
    float* sA  = smem;               // P4 A
    float* sB4 = smem + 4608;        // P4 B
    float* p1A = smem;               // P1 A
    float* p1B = smem + 4352;        // P1 B
    float* s2A = smem;               // P2 A
    float* s2B = smem + 2112;        // P2 B
    float* sred  = smem + 4672;
    float* sred2 = smem + 4688;

    const int tid = threadIdx.x;
    const int bid = blockIdx.x;

    int gen = g_release;

    // init state (+ reset flags/counters each replay)
    for (int i = bid * NTHR + tid; i < Bsz * Hsz; i += NBLK * NTHR) {
        g_h[i] = 0.f; g_c[i] = 0.f;
    }
    if (bid == 0 && tid < 32) {
        g_x1flag[tid] = 0;
        g_tilecnt[tid] = 0;
        g_cnt1[tid] = 0;
    }
    grid_sync(gen);

    // P1 decode: 32 tiles (8 row x 4 col of 32x32) x 4-way K-split (128)
    const int tile1 = bid >> 2, ks1 = bid & 3;
    const int r0_1 = (tile1 >> 2) * 32, n0_1 = (tile1 & 3) * 32;
    const int k0_1 = ks1 * 128;
    const bool wr_xvec = ((tile1 & 3) == 0);
    const int p1r = tid >> 4, p1n = tid & 15;     // row 0..31, col-pair 0..15

    // P2 decode: 128 tiles of 16x16, pair-split K (kh in {0,1})
    const int r0_2 = (bid >> 3) * 16, n0_2 = (bid & 7) * 16;
    const int rb = bid >> 4;
    const int cell = tid >> 1, kh = tid & 1;
    const int c_r = cell >> 4, c_n = cell & 15;

    // P4 decode: 32 tiles (2 row x 16 col of 128x128) x 4-way K-split (192)
    const int ks4  = bid & 3;
    const int tile4 = bid >> 2;
    const int b0B = (tile4 >> 4) * 128;
    const int n0_4 = (tile4 & 15) * 128;
    const int k0b = ks4 * 192;
    const int ty4 = tid >> 4, tx4 = tid & 15;     // rows ty4*4.., cols tx4*8..

#pragma unroll 1
    for (int t = 0; t < Tsz; t++) {
        // ================= P1: x_hist GEMM 32x32xK128 (decay folded into A-load) =================
        {
#pragma unroll
            for (int q = 0; q < 2; q++) {
                int i = tid + q * NTHR;          // f4 index 0..1023
                int row = i >> 5, kq = i & 31;
                const float4 hv4 = *reinterpret_cast<const float4*>(
                    &g_h[(r0_1 + row) * Hsz + k0_1 + kq * 4]);
                const float4 gv4 = *reinterpret_cast<const float4*>(
                    &g_gamma_h[((size_t)(r0_1 + row) * Tsz + t) * Hsz + k0_1 + kq * 4]);
                float4 o;
                o.x = hv4.x * gv4.x; o.y = hv4.y * gv4.y;
                o.z = hv4.z * gv4.z; o.w = hv4.w * gv4.w;
                *reinterpret_cast<float4*>(&p1A[row * 136 + kq * 4]) = o;
                if (wr_xvec)
                    *reinterpret_cast<float4*>(
                        &g_xvec[(r0_1 + row) * KC + Fsz + k0_1 + kq * 4]) = o;
            }
#pragma unroll
            for (int q = 0; q < 2; q++) {
                int i = tid + q * NTHR;          // f4 index 0..1023
                int k = i >> 3, nq = i & 7;
                float4 v = *reinterpret_cast<const float4*>(
                    &g_histT[(k0_1 + k) * Fsz + n0_1 + nq * 4]);
                *reinterpret_cast<float4*>(&p1B[k * 36 + nq * 4]) = v;
            }
            __syncthreads();
            ull acc0 = 0ull;
#pragma unroll 8
            for (int k = 0; k < 128; k++) {
                ull b2 = *reinterpret_cast<ull*>(&p1B[k * 36 + p1n * 2]);
                ull ad;
                DUP32(ad, __float_as_uint(p1A[p1r * 136 + k]));
                FMA2(acc0, ad, b2);
            }
            *reinterpret_cast<ull*>(
                &g_p1part[(tile1 * 4 + ks1) * 1024 + p1r * 32 + p1n * 2]) = acc0;
            __threadfence();
            __syncthreads();
            if (tid == 0) {
                int old = atomicAdd(&g_cnt1[tile1], 1);
                s_last = (old == 3);
            }
            __syncthreads();
            if (s_last) {
                __threadfence();
                size_t tb = (size_t)tile1 * 4 * 1024;
#pragma unroll
                for (int q = 0; q < 2; q++) {
                    int idx = tid + q * NTHR;
                    int r = idx >> 5, n = idx & 31;
                    float v = ((g_p1part[tb + idx] + g_p1part[tb + 1024 + idx]) +
                               (g_p1part[tb + 2048 + idx] + g_p1part[tb + 3072 + idx])) +
                              hist_b[n0_1 + n];
                    g_xhist[(r0_1 + r) * Fsz + n0_1 + n] = v;
                }
                __threadfence();
                __syncthreads();
                if (tid == 0) {
                    g_cnt1[tile1] = 0;
                    g_x1flag[tile1] = t + 1;   // publish
                }
            }
        }

        // ================= P2: z_h GEMM 16x16xK128 + elementwise + loss =================
        {
            if (tid < 4) {
                while (g_x1flag[rb * 4 + tid] - (t + 1) < 0) { }
            }
            __syncthreads();
            __threadfence();   // acquire (also flushes stale L1)

            {
                int i = tid;                     // f4 index 0..511
                int row = i >> 5, kq = i & 31;
                size_t base = ((size_t)(r0_2 + row) * Tsz + t) * Fsz + kq * 4;
                float4 mv = *reinterpret_cast<const float4*>(&m[base]);
                float4 xv = *reinterpret_cast<const float4*>(&x[base]);
                float4 xh = *reinterpret_cast<const float4*>(
                    &g_xhist[(r0_2 + row) * Fsz + kq * 4]);
                float4 o;
                o.x = mv.x * xv.x + (1.f - mv.x) * xh.x;
                o.y = mv.y * xv.y + (1.f - mv.y) * xh.y;
                o.z = mv.z * xv.z + (1.f - mv.z) * xh.z;
                o.w = mv.w * xv.w + (1.f - mv.w) * xh.w;
                *reinterpret_cast<float4*>(&s2A[row * 132 + kq * 4]) = o;
            }
            {
                int i = tid;                     // f4 index 0..511
                int k = i >> 2, nq = i & 3;
                float4 v = *reinterpret_cast<const float4*>(
                    &g_featMT[k * Fsz + n0_2 + nq * 4]);
                *reinterpret_cast<float4*>(&s2B[k * 20 + nq * 4]) = v;
            }
            __syncthreads();

            float z0 = 0.f, z1 = 0.f, z2 = 0.f, z3 = 0.f;
            const float* arow = s2A + c_r * 132 + kh * 64;
            const float* bcol = s2B + kh * 64 * 20 + c_n;
#pragma unroll 8
            for (int k = 0; k < 64; k += 4) {
                z0 += arow[k]     * bcol[(k)     * 20];
                z1 += arow[k + 1] * bcol[(k + 1) * 20];
                z2 += arow[k + 2] * bcol[(k + 2) * 20];
                z3 += arow[k + 3] * bcol[(k + 3) * 20];
            }
            float zh = (z0 + z1) + (z2 + z3);
            zh += __shfl_xor_sync(0xffffffffu, zh, 1);

            float lp = 0.f, es = 0.f;
            if (kh == 0) {
                int r = r0_2 + c_r, n = n0_2 + c_n;
                size_t base = ((size_t)r * Tsz + t) * Fsz + n;
                float z = zh + feat_b[n];
                float xh = g_xhist[r * Fsz + n];
                float a = g_alpha[base];
                float mv = m[base], xv = x[base];
                float ch = a * z + (1.f - a) * xh;
                float cc = mv * xv + (1.f - mv) * ch;
                g_xvec[r * KC + n] = cc;
                g_xvec[r * KC + (Fsz + Hsz) + n] = mv;
                out[base] = cc;
                float ev = target_mask[base];
                float tg = target_x[base];
                float d1 = xh - tg, d2 = z - tg, d3 = ch - tg;
                lp = ev * (d1 * d1 + d2 * d2 + d3 * d3);
                es = ev;
            }
            for (int o = 16; o; o >>= 1) {
                lp += __shfl_down_sync(0xffffffffu, lp, o);
                es += __shfl_down_sync(0xffffffffu, es, o);
            }
            if ((tid & 31) == 0) { sred[tid >> 5] = lp; sred2[tid >> 5] = es; }
            __syncthreads();
            if (tid == 0) {
                float tot = 0.f, tot2 = 0.f;
                for (int i = 0; i < 16; i++) { tot += sred[i]; tot2 += sred2[i]; }
                g_losspart[t * 128 + bid] = tot;
                g_maskpart[t * 128 + bid] = tot2;
            }
        }
        grid_sync(gen);

        // ================= P4: gate GEMM 128x128x192 split-K, micro 4x8 =================
        {
            ull acc[4][4];
#pragma unroll
            for (int i = 0; i < 4; i++)
#pragma unroll
                for (int j = 0; j < 4; j++) acc[i][j] = 0ull;

            float4 pa[2], pb[2];
#pragma unroll
            for (int q = 0; q < 2; q++) {
                int i = tid + q * NTHR;          // f4 0..1023
                int mm = i >> 3, kq = i & 7;
                pa[q] = *reinterpret_cast<const float4*>(
                    &g_xvec[(b0B + mm) * KC + k0b + kq * 4]);
            }
#pragma unroll
            for (int q = 0; q < 2; q++) {
                int i = tid + q * NTHR;          // f4 0..1023
                int kk = i >> 5, nq = i & 31;
                pb[q] = *reinterpret_cast<const float4*>(
                    &g_WcombT[(size_t)(k0b + kk) * N4H + n0_4 + nq * 4]);
            }

#pragma unroll 1
            for (int kb = 0; kb < 6; kb++) {
                __syncthreads();
#pragma unroll
                for (int q = 0; q < 2; q++) {
                    int i = tid + q * NTHR;
                    int mm = i >> 3, kq = i & 7;
                    *reinterpret_cast<float4*>(&sA[mm * 36 + kq * 4]) = pa[q];
                }
#pragma unroll
                for (int q = 0; q < 2; q++) {
                    int i = tid + q * NTHR;
                    int kk = i >> 5, nq = i & 31;
                    *reinterpret_cast<float4*>(&sB4[kk * 132 + nq * 4]) = pb[q];
                }
                __syncthreads();
                if (kb < 5) {
                    const int k0n = k0b + (kb + 1) * 32;
#pragma unroll
                    for (int q = 0; q < 2; q++) {
                        int i = tid + q * NTHR;
                        int mm = i >> 3, kq = i & 7;
                        pa[q] = *reinterpret_cast<const float4*>(
                            &g_xvec[(b0B + mm) * KC + k0n + kq * 4]);
                    }
#pragma unroll
                    for (int q = 0; q < 2; q++) {
                        int i = tid + q * NTHR;
                        int kk = i >> 5, nq = i & 31;
                        pb[q] = *reinterpret_cast<const float4*>(
                            &g_WcombT[(size_t)(k0n + kk) * N4H + n0_4 + nq * 4]);
                    }
                }
#pragma unroll 8
                for (int k = 0; k < 32; k++) {
                    ulonglong2 bb0 = *reinterpret_cast<const ulonglong2*>(
                        &sB4[k * 132 + tx4 * 8]);
                    ulonglong2 bb1 = *reinterpret_cast<const ulonglong2*>(
                        &sB4[k * 132 + tx4 * 8 + 4]);
#pragma unroll
                    for (int r2 = 0; r2 < 4; r2++) {
                        ull ad;
                        DUP32(ad, __float_as_uint(sA[(ty4 * 4 + r2) * 36 + k]));
                        FMA2(acc[r2][0], ad, bb0.x);
                        FMA2(acc[r2][1], ad, bb0.y);
                        FMA2(acc[r2][2], ad, bb1.x);
                        FMA2(acc[r2][3], ad, bb1.y);
                    }
                }
            }

            // store partials
            size_t pbase = (size_t)(tile4 * 4 + ks4) * 16384;
#pragma unroll
            for (int r2 = 0; r2 < 4; r2++) {
#pragma unroll
                for (int cp = 0; cp < 4; cp++) {
                    size_t off = pbase + (size_t)(ty4 * 4 + r2) * 128 + tx4 * 8 + cp * 2;
                    *reinterpret_cast<ull*>(&g_part[off]) = acc[r2][cp];
                }
            }
            __threadfence();
            __syncthreads();
            if (tid == 0) {
                atomicAdd(&g_tilecnt[tile4], 1);
                while (*(volatile int*)&g_tilecnt[tile4] - 4 * (t + 1) < 0) { }
            }
            __syncthreads();
            __threadfence();   // acquire + L1 flush

            // even epilogue: each K-block handles its 32-row quarter of the tile
            size_t tb = (size_t)tile4 * 4 * 16384;
            float4 bc = *reinterpret_cast<const float4*>(&g_bcomb[n0_4 + (tid & 31) * 4]);
#pragma unroll
            for (int q = 0; q < 2; q++) {
                int idx = tid + q * NTHR;        // 0..1023 f4-cells
                int row = ks4 * 32 + (idx >> 5), u = idx & 31;
                size_t go_off = (size_t)row * 128 + u * 4;
                float4 p0 = *reinterpret_cast<const float4*>(&g_part[tb + go_off]);
                float4 p1 = *reinterpret_cast<const float4*>(&g_part[tb + 16384 + go_off]);
                float4 p2 = *reinterpret_cast<const float4*>(&g_part[tb + 32768 + go_off]);
                float4 p3 = *reinterpret_cast<const float4*>(&g_part[tb + 49152 + go_off]);
                float gi = ((p0.x + p1.x) + (p2.x + p3.x)) + bc.x;
                float gf = ((p0.y + p1.y) + (p2.y + p3.y)) + bc.y;
                float gg = ((p0.z + p1.z) + (p2.z + p3.z)) + bc.z;
                float gO = ((p0.w + p1.w) + (p2.w + p3.w)) + bc.w;
                float si = sigap(gi);
                float sf = sigap(gf);
                float so = sigap(gO);
                float tg = tanhap(gg);
                int b = b0B + row;
                int j = (n0_4 >> 2) + u;
                float cn = sf * g_c[b * Hsz + j] + si * tg;
                g_c[b * Hsz + j] = cn;
                g_h[b * Hsz + j] = so * tanhap(cn);
            }
        }
        grid_sync(gen);
    }
}

// ----------------------------------------------------------------------
__global__ void loss_final(float* __restrict__ out, int out_size) {
    __shared__ float s[128];
    int t = threadIdx.x;
    float v = 0.f, mv = 0.f;
    for (int p = 0; p < 128; p++) {
        v += g_losspart[t * 128 + p];
        mv += g_maskpart[t * 128 + p];
    }
    s[t] = v / (mv + 1e-8f);
    __syncthreads();
    if (t == 0) {
        float tot = 0.f;
        for (int i = 0; i < 128; i++) tot += s[i];
        out[out_size - 1] = tot / (float)Tsz;
    }
}

// ----------------------------------------------------------------------
extern "C" void kernel_launch(void* const* d_in, const int* in_sizes, int n_in,
                              void* d_out, int out_size) {
    const float* x           = (const float*)d_in[0];
    const float* m           = (const float*)d_in[1];
    const float* d           = (const float*)d_in[2];
    const float* target_x    = (const float*)d_in[3];
    const float* target_mask = (const float*)d_in[4];
    const float* td_h_W      = (const float*)d_in[5];
    const float* td_h_b      = (const float*)d_in[6];
    const float* td_x_W      = (const float*)d_in[7];
    const float* td_x_b      = (const float*)d_in[8];
    const float* hist_W      = (const float*)d_in[9];
    const float* hist_b      = (const float*)d_in[10];
    const float* feat_W      = (const float*)d_in[11];
    const float* feat_b      = (const float*)d_in[12];
    const float* wc_W        = (const float*)d_in[13];
    const float* wc_b        = (const float*)d_in[14];
    const float* W_ih        = (const float*)d_in[15];
    const float* W_hh        = (const float*)d_in[16];
    const float* b_ih        = (const float*)d_in[17];
    const float* b_hh        = (const float*)d_in[18];
    float* out = (float*)d_out;

    prep_weights<<<512, 256>>>(td_h_W, hist_W, feat_W, wc_W, W_ih, W_hh, b_ih, b_hh);
    gammah_gemm<<<dim3(BT / 64, Hsz / 64), 256>>>(d, td_h_b);
    alpha_gemm<<<dim3(BT / 64, Fsz / 64), 256>>>(d, m, td_x_W, td_x_b, wc_b);

    rits_persistent<<<NBLK, NTHR>>>(x, m, target_x, target_mask, hist_b, feat_b, out);

    loss_final<<<1, 128>>>(out, out_size);
}

// round 11
// speedup vs baseline: 1.0383x; 1.0087x over previous
#include <cuda_runtime.h>
#include <math.h>

#define Bsz 256
#define Tsz 128
#define Fsz 128
#define Hsz 512
#define BT  (Bsz * Tsz)          // 32768
#define KC  768                  // c_c(128) + h_dec(512) + m(128)
#define N4H 2048                 // 4*H, gate-interleaved
#define NBLK 128                 // persistent grid size
#define NTHR 512

typedef unsigned long long ull;

// ----- device scratch (allocation-free rule: __device__ globals) -----
__device__ __align__(16) float g_h[Bsz * Hsz];
__device__ __align__(16) float g_c[Bsz * Hsz];
__device__ __align__(16) float g_xvec[Bsz * KC];
__device__ __align__(16) float g_gamma_h[(size_t)BT * Hsz];   // 64 MB
__device__ __align__(16) float g_alpha[BT * Fsz];
__device__ float g_losspart[Tsz * 128];
__device__ float g_maskpart[Tsz * 128];
__device__ __align__(16) float g_tdhT[Fsz * Hsz];
__device__ __align__(16) float g_histT[Hsz * Fsz];            // [k][f]
__device__ __align__(16) float g_featMT[Fsz * Fsz];           // [j][f]
__device__ __align__(16) float g_wcT[2 * Fsz * Fsz];
__device__ __align__(16) float g_WcombT[KC * N4H];
__device__ __align__(16) float g_bcomb[N4H];
__device__ __align__(16) float g_part[(size_t)32 * 4 * 128 * 128];  // P4 split-K partials
__device__ int g_tilecnt[32];            // monotone within a replay

// flag-array grid barrier
__device__ volatile int g_arrive[NBLK];
__device__ volatile int g_release;

__device__ __forceinline__ float fsigmoid(float v) {
    return __fdividef(1.f, 1.f + __expf(-v));
}
__device__ __forceinline__ float tanhap(float x) {
    float r;
    asm("tanh.approx.f32 %0, %1;" : "=f"(r) : "f"(x));
    return r;
}
__device__ __forceinline__ float sigap(float v) {
    return 0.5f * tanhap(0.5f * v) + 0.5f;
}

// ----------------------------------------------------------------------
__global__ void prep_weights(const float* __restrict__ td_h_W,
                             const float* __restrict__ hist_W,
                             const float* __restrict__ feat_W,
                             const float* __restrict__ wc_W,
                             const float* __restrict__ W_ih,
                             const float* __restrict__ W_hh,
                             const float* __restrict__ b_ih,
                             const float* __restrict__ b_hh) {
    int stride = gridDim.x * blockDim.x;
    int tid = blockIdx.x * blockDim.x + threadIdx.x;
    for (int i = tid; i < Fsz * Hsz; i += stride) {
        int k = i / Hsz, n = i % Hsz;
        g_tdhT[i] = td_h_W[n * Fsz + k];
    }
    for (int i = tid; i < Hsz * Fsz; i += stride) {
        int k = i / Fsz, f = i % Fsz;
        g_histT[i] = hist_W[f * Hsz + k];
    }
    for (int i = tid; i < Fsz * Fsz; i += stride) {
        int j = i / Fsz, f = i % Fsz;
        g_featMT[i] = (j == f) ? 0.f : feat_W[f * Fsz + j];
    }
    for (int i = tid; i < 2 * Fsz * Fsz; i += stride) {
        int k = i / Fsz, n = i % Fsz;
        g_wcT[i] = wc_W[n * 2 * Fsz + k];
    }
    for (int i = tid; i < KC * N4H; i += stride) {
        int k = i / N4H, n = i % N4H;
        int j = n >> 2, g = n & 3;
        int row = g * Hsz + j;
        float v;
        if (k < Fsz)            v = W_ih[row * (2 * Fsz) + k];
        else if (k < Fsz + Hsz) v = W_hh[row * Hsz + (k - Fsz)];
        else                    v = W_ih[row * (2 * Fsz) + Fsz + (k - Fsz - Hsz)];
        g_WcombT[i] = v;
    }
    for (int i = tid; i < N4H; i += stride) {
        int j = i >> 2, g = i & 3;
        g_bcomb[i] = b_ih[g * Hsz + j] + b_hh[g * Hsz + j];
    }
}

// ----------------------------------------------------------------------
__global__ void gammah_gemm(const float* __restrict__ d,
                            const float* __restrict__ td_h_b) {
    __shared__ float sA[64][33];
    __shared__ float sB[32][64];
    int m0 = blockIdx.x * 64;
    int n0 = blockIdx.y * 64;
    int tid = threadIdx.x;
    int tx = tid & 15, ty = tid >> 4;
    float acc[4][4] = {};
    for (int kk = 0; kk < Fsz; kk += 32) {
        for (int i = tid; i < 64 * 32; i += 256) {
            int r = i >> 5, k = i & 31;
            sA[r][k] = d[(size_t)(m0 + r) * Fsz + kk + k];
        }
        for (int i = tid; i < 32 * 64; i += 256) {
            int k = i >> 6, n = i & 63;
            sB[k][n] = g_tdhT[(kk + k) * Hsz + n0 + n];
        }
        __syncthreads();
#pragma unroll
        for (int k = 0; k < 32; k++) {
            float a[4], b[4];
#pragma unroll
            for (int i = 0; i < 4; i++) a[i] = sA[ty + i * 16][k];
#pragma unroll
            for (int j = 0; j < 4; j++) b[j] = sB[k][tx + j * 16];
#pragma unroll
            for (int i = 0; i < 4; i++)
#pragma unroll
                for (int j = 0; j < 4; j++) acc[i][j] += a[i] * b[j];
        }
        __syncthreads();
    }
#pragma unroll
    for (int i = 0; i < 4; i++)
#pragma unroll
        for (int j = 0; j < 4; j++) {
            int n = n0 + tx + j * 16;
            int row = m0 + ty + i * 16;
            g_gamma_h[(size_t)row * Hsz + n] = __expf(-fmaxf(acc[i][j] + td_h_b[n], 0.f));
        }
}

// ----------------------------------------------------------------------
__global__ void alpha_gemm(const float* __restrict__ d,
                           const float* __restrict__ m,
                           const float* __restrict__ td_x_W,
                           const float* __restrict__ td_x_b,
                           const float* __restrict__ wc_b) {
    __shared__ float sA[64][33];
    __shared__ float sB[32][64];
    int m0 = blockIdx.x * 64;
    int n0 = blockIdx.y * 64;
    int tid = threadIdx.x;
    int tx = tid & 15, ty = tid >> 4;
    float acc[4][4] = {};
    for (int kk = 0; kk < 2 * Fsz; kk += 32) {
        for (int i = tid; i < 64 * 32; i += 256) {
            int r = i >> 5, k = i & 31;
            int kg = kk + k;
            float v;
            if (kg < Fsz) {
                float dv = d[(size_t)(m0 + r) * Fsz + kg];
                float u = dv * td_x_W[kg * Fsz + kg] + td_x_b[kg];
                v = __expf(-fmaxf(u, 0.f));
            } else {
                v = m[(size_t)(m0 + r) * Fsz + (kg - Fsz)];
            }
            sA[r][k] = v;
        }
        for (int i = tid; i < 32 * 64; i += 256) {
            int k = i >> 6, n = i & 63;
            sB[k][n] = g_wcT[(kk + k) * Fsz + n0 + n];
        }
        __syncthreads();
#pragma unroll
        for (int k = 0; k < 32; k++) {
            float a[4], b[4];
#pragma unroll
            for (int i = 0; i < 4; i++) a[i] = sA[ty + i * 16][k];
#pragma unroll
            for (int j = 0; j < 4; j++) b[j] = sB[k][tx + j * 16];
#pragma unroll
            for (int i = 0; i < 4; i++)
#pragma unroll
                for (int j = 0; j < 4; j++) acc[i][j] += a[i] * b[j];
        }
        __syncthreads();
    }
#pragma unroll
    for (int i = 0; i < 4; i++)
#pragma unroll
        for (int j = 0; j < 4; j++) {
            int n = n0 + tx + j * 16;
            int row = m0 + ty + i * 16;
            float v = acc[i][j] + wc_b[n];
            g_alpha[row * Fsz + n] = fsigmoid(v);
        }
}

// ======================================================================
#define FMA2(acc, a2, b2) \
    asm("fma.rn.f32x2 %0, %1, %2, %0;" : "+l"(acc) : "l"(a2), "l"(b2))
#define DUP32(d, s) \
    asm("mov.b64 %0, {%1, %1};" : "=l"(d) : "r"(s))

// flag-array barrier: one STG per block, block 0 gathers, no atomic contention
__device__ __forceinline__ void grid_sync(int& gen) {
    gen++;
    __threadfence();
    __syncthreads();
    if (blockIdx.x == 0) {
        int tid = threadIdx.x;
        if (tid > 0 && tid < NBLK) {
            while (g_arrive[tid] - gen < 0) { }
        }
        __syncthreads();
        if (tid == 0) g_release = gen;
    } else {
        if (threadIdx.x == 0) {
            g_arrive[blockIdx.x] = gen;
            while (g_release - gen < 0) { }
        }
    }
    __syncthreads();
    __threadfence();
}

// smem layout (floats):
//  phase A: sW[64*132]=8448 @0 | sh[2*512]=1024 @8448 | sxc[2*128]=256 @9472
//           spart[512] @9728 | sred[16] @10240 | sred2[16] @10256   (total 10272)
//  P4:      sA[128*36]=4608 @0 | sB4[32*132]=4224 @4608               (total 8832)
#define SMEMF 10272

__global__ void __launch_bounds__(NTHR, 1)
rits_persistent(const float* __restrict__ x,
                const float* __restrict__ m,
                const float* __restrict__ target_x,
                const float* __restrict__ target_mask,
                const float* __restrict__ hist_b,
                const float* __restrict__ feat_b,
                float* __restrict__ out) {
    __shared__ __align__(16) float smem[SMEMF];
    float* sW    = smem;
    float* sh    = smem + 8448;
    float* sxc   = smem + 9472;
    float* spart = smem + 9728;
    float* sred  = smem + 10240;
    float* sred2 = smem + 10256;
    float* sA  = smem;               // P4 A
    float* sB4 = smem + 4608;        // P4 B

    const int tid = threadIdx.x;
    const int bid = blockIdx.x;

    int gen = g_release;

    // init state (+ reset counters each replay)
    for (int i = bid * NTHR + tid; i < Bsz * Hsz; i += NBLK * NTHR) {
        g_h[i] = 0.f; g_c[i] = 0.f;
    }
    if (bid == 0 && tid < 32) g_tilecnt[tid] = 0;
    grid_sync(gen);

    // phase A decode: block owns rows 2*bid, 2*bid+1
    const int rows0 = 2 * bid;
    const int fA = tid & 127;
    const int rA = (tid >> 7) & 1;
    const int dA = tid >> 8;               // k-parity split

    // P4 decode: 32 tiles (2 row x 16 col of 128x128) x 4-way K-split (192)
    const int ks4  = bid & 3;
    const int tile4 = bid >> 2;
    const int b0B = (tile4 >> 4) * 128;
    const int n0_4 = (tile4 & 15) * 128;
    const int k0b = ks4 * 192;
    const int ty4 = tid >> 4, tx4 = tid & 15;

#pragma unroll 1
    for (int t = 0; t < Tsz; t++) {
        // ================= Phase A: fully row-local, no inter-block deps =================
        {
            // h_dec = h * gamma_h -> sh + xvec (threads 0..255, f4 each)
            if (tid < 256) {
                int r = tid >> 7, kq = tid & 127;
                const float4 h4 = *reinterpret_cast<const float4*>(
                    &g_h[(rows0 + r) * Hsz + kq * 4]);
                const float4 g4 = *reinterpret_cast<const float4*>(
                    &g_gamma_h[((size_t)(rows0 + r) * Tsz + t) * Hsz + kq * 4]);
                float4 o;
                o.x = h4.x * g4.x; o.y = h4.y * g4.y;
                o.z = h4.z * g4.z; o.w = h4.w * g4.w;
                *reinterpret_cast<float4*>(&sh[r * 512 + kq * 4]) = o;
                *reinterpret_cast<float4*>(
                    &g_xvec[(rows0 + r) * KC + Fsz + kq * 4]) = o;
            }

            // x_hist: acc over K=512 (parity-split by dA), histT staged in 64-row chunks
            float acc = 0.f;
#pragma unroll 1
            for (int kb = 0; kb < 8; kb++) {
                const int k0 = kb * 64;
                __syncthreads();
#pragma unroll
                for (int q = 0; q < 4; q++) {
                    int i = tid + q * NTHR;        // 0..2047 f4-cells
                    int k = i >> 5, fq = i & 31;
                    float4 v = *reinterpret_cast<const float4*>(
                        &g_histT[(k0 + k) * Fsz + fq * 4]);
                    *reinterpret_cast<float4*>(&sW[k * 132 + fq * 4]) = v;
                }
                __syncthreads();
                const float* shr = sh + rA * 512 + k0;
#pragma unroll 8
                for (int k = dA; k < 64; k += 2)
                    acc += shr[k] * sW[k * 132 + fA];
            }
            spart[tid] = acc;
            __syncthreads();

            float xh = 0.f, mv = 0.f, xv = 0.f;
            size_t base = 0;
            if (tid < 256) {
                xh = spart[tid] + spart[tid + 256] + hist_b[fA];
                base = ((size_t)(rows0 + rA) * Tsz + t) * Fsz + fA;
                mv = m[base]; xv = x[base];
                float xc = mv * xv + (1.f - mv) * xh;
                sxc[rA * 128 + fA] = xc;
                g_xvec[(rows0 + rA) * KC + (Fsz + Hsz) + fA] = mv;
            }

            // z_h: acc over J=128 (parity-split), featMT staged in 2 chunks
            float accz = 0.f;
#pragma unroll 1
            for (int jb = 0; jb < 2; jb++) {
                const int j0 = jb * 64;
                __syncthreads();
#pragma unroll
                for (int q = 0; q < 4; q++) {
                    int i = tid + q * NTHR;
                    int j = i >> 5, fq = i & 31;
                    float4 v = *reinterpret_cast<const float4*>(
                        &g_featMT[(j0 + j) * Fsz + fq * 4]);
                    *reinterpret_cast<float4*>(&sW[j * 132 + fq * 4]) = v;
                }
                __syncthreads();
                const float* sxr = sxc + rA * 128 + j0;
#pragma unroll 8
                for (int j = dA; j < 64; j += 2)
                    accz += sxr[j] * sW[j * 132 + fA];
            }
            spart[tid] = accz;
            __syncthreads();

            float lp = 0.f, es = 0.f;
            if (tid < 256) {
                float z = spart[tid] + spart[tid + 256] + feat_b[fA];
                float a = g_alpha[base];
                float ch = a * z + (1.f - a) * xh;
                float cc = mv * xv + (1.f - mv) * ch;
                g_xvec[(rows0 + rA) * KC + fA] = cc;
                out[base] = cc;
                float ev = target_mask[base];
                float tg = target_x[base];
                float d1 = xh - tg, d2 = z - tg, d3 = ch - tg;
                lp = ev * (d1 * d1 + d2 * d2 + d3 * d3);
                es = ev;
            }
            for (int o = 16; o; o >>= 1) {
                lp += __shfl_down_sync(0xffffffffu, lp, o);
                es += __shfl_down_sync(0xffffffffu, es, o);
            }
            if ((tid & 31) == 0) { sred[tid >> 5] = lp; sred2[tid >> 5] = es; }
            __syncthreads();
            if (tid == 0) {
                float tot = 0.f, tot2 = 0.f;
                for (int i = 0; i < 8; i++) { tot += sred[i]; tot2 += sred2[i]; }
                g_losspart[t * 128 + bid] = tot;
                g_maskpart[t * 128 + bid] = tot2;
            }
        }
        grid_sync(gen);

        // ================= P4: gate GEMM 128x128x192 split-K, micro 4x8 =================
        {
            ull acc[4][4];
#pragma unroll
            for (int i = 0; i < 4; i++)
#pragma unroll
                for (int j = 0; j < 4; j++) acc[i][j] = 0ull;

            float4 pa[2], pb[2];
#pragma unroll
            for (int q = 0; q < 2; q++) {
                int i = tid + q * NTHR;
                int mm = i >> 3, kq = i & 7;
                pa[q] = *reinterpret_cast<const float4*>(
                    &g_xvec[(b0B + mm) * KC + k0b + kq * 4]);
            }
#pragma unroll
            for (int q = 0; q < 2; q++) {
                int i = tid + q * NTHR;
                int kk = i >> 5, nq = i & 31;
                pb[q] = *reinterpret_cast<const float4*>(
                    &g_WcombT[(size_t)(k0b + kk) * N4H + n0_4 + nq * 4]);
            }

#pragma unroll 1
            for (int kb = 0; kb < 6; kb++) {
                __syncthreads();
#pragma unroll
                for (int q = 0; q < 2; q++) {
                    int i = tid + q * NTHR;
                    int mm = i >> 3, kq = i & 7;
                    *reinterpret_cast<float4*>(&sA[mm * 36 + kq * 4]) = pa[q];
                }
#pragma unroll
                for (int q = 0; q < 2; q++) {
                    int i = tid + q * NTHR;
                    int kk = i >> 5, nq = i & 31;
                    *reinterpret_cast<float4*>(&sB4[kk * 132 + nq * 4]) = pb[q];
                }
                __syncthreads();
                if (kb < 5) {
                    const int k0n = k0b + (kb + 1) * 32;
#pragma unroll
                    for (int q = 0; q < 2; q++) {
                        int i = tid + q * NTHR;
                        int mm = i >> 3, kq = i & 7;
                        pa[q] = *reinterpret_cast<const float4*>(
                            &g_xvec[(b0B + mm) * KC + k0n + kq * 4]);
                    }
#pragma unroll
                    for (int q = 0; q < 2; q++) {
                        int i = tid + q * NTHR;
                        int kk = i >> 5, nq = i & 31;
                        pb[q] = *reinterpret_cast<const float4*>(
                            &g_WcombT[(size_t)(k0n + kk) * N4H + n0_4 + nq * 4]);
                    }
                }
#pragma unroll 8
                for (int k = 0; k < 32; k++) {
                    ulonglong2 bb0 = *reinterpret_cast<const ulonglong2*>(
                        &sB4[k * 132 + tx4 * 8]);
                    ulonglong2 bb1 = *reinterpret_cast<const ulonglong2*>(
                        &sB4[k * 132 + tx4 * 8 + 4]);
#pragma unroll
                    for (int r2 = 0; r2 < 4; r2++) {
                        ull ad;
                        DUP32(ad, __float_as_uint(sA[(ty4 * 4 + r2) * 36 + k]));
                        FMA2(acc[r2][0], ad, bb0.x);
                        FMA2(acc[r2][1], ad, bb0.y);
                        FMA2(acc[r2][2], ad, bb1.x);
                        FMA2(acc[r2][3], ad, bb1.y);
                    }
                }
            }

            // store partials
            size_t pbase = (size_t)(tile4 * 4 + ks4) * 16384;
#pragma unroll
            for (int r2 = 0; r2 < 4; r2++) {
#pragma unroll
                for (int cp = 0; cp < 4; cp++) {
                    size_t off = pbase + (size_t)(ty4 * 4 + r2) * 128 + tx4 * 8 + cp * 2;
                    *reinterpret_cast<ull*>(&g_part[off]) = acc[r2][cp];
                }
            }
            __threadfence();
            __syncthreads();
            if (tid == 0) {
                atomicAdd(&g_tilecnt[tile4], 1);
                while (*(volatile int*)&g_tilecnt[tile4] - 4 * (t + 1) < 0) { }
            }
            __syncthreads();
            __threadfence();   // acquire

            // even epilogue: each K-block handles its 32-row quarter of the tile
            size_t tb = (size_t)tile4 * 4 * 16384;
            float4 bc = *reinterpret_cast<const float4*>(&g_bcomb[n0_4 + (tid & 31) * 4]);
#pragma unroll
            for (int q = 0; q < 2; q++) {
                int idx = tid + q * NTHR;        // 0..1023 f4-cells
                int row = ks4 * 32 + (idx >> 5), u = idx & 31;
                size_t go_off = (size_t)row * 128 + u * 4;
                float4 p0 = *reinterpret_cast<const float4*>(&g_part[tb + go_off]);
                float4 p1 = *reinterpret_cast<const float4*>(&g_part[tb + 16384 + go_off]);
                float4 p2 = *reinterpret_cast<const float4*>(&g_part[tb + 32768 + go_off]);
                float4 p3 = *reinterpret_cast<const float4*>(&g_part[tb + 49152 + go_off]);
                float gi = ((p0.x + p1.x) + (p2.x + p3.x)) + bc.x;
                float gf = ((p0.y + p1.y) + (p2.y + p3.y)) + bc.y;
                float gg = ((p0.z + p1.z) + (p2.z + p3.z)) + bc.z;
                float gO = ((p0.w + p1.w) + (p2.w + p3.w)) + bc.w;
                float si = sigap(gi);
                float sf = sigap(gf);
                float so = sigap(gO);
                float tg = tanhap(gg);
                int b = b0B + row;
                int j = (n0_4 >> 2) + u;
                float cn = sf * g_c[b * Hsz + j] + si * tg;
                g_c[b * Hsz + j] = cn;
                g_h[b * Hsz + j] = so * tanhap(cn);
            }
        }
        grid_sync(gen);
    }
}

// ----------------------------------------------------------------------
__global__ void loss_final(float* __restrict__ out, int out_size) {
    __shared__ float s[128];
    int t = threadIdx.x;
    float v = 0.f, mv = 0.f;
    for (int p = 0; p < 128; p++) {
        v += g_losspart[t * 128 + p];
        mv += g_maskpart[t * 128 + p];
    }
    s[t] = v / (mv + 1e-8f);
    __syncthreads();
    if (t == 0) {
        float tot = 0.f;
        for (int i = 0; i < 128; i++) tot += s[i];
        out[out_size - 1] = tot / (float)Tsz;
    }
}

// ----------------------------------------------------------------------
extern "C" void kernel_launch(void* const* d_in, const int* in_sizes, int n_in,
                              void* d_out, int out_size) {
    const float* x           = (const float*)d_in[0];
    const float* m           = (const float*)d_in[1];
    const float* d           = (const float*)d_in[2];
    const float* target_x    = (const float*)d_in[3];
    const float* target_mask = (const float*)d_in[4];
    const float* td_h_W      = (const float*)d_in[5];
    const float* td_h_b      = (const float*)d_in[6];
    const float* td_x_W      = (const float*)d_in[7];
    const float* td_x_b      = (const float*)d_in[8];
    const float* hist_W      = (const float*)d_in[9];
    const float* hist_b      = (const float*)d_in[10];
    const float* feat_W      = (const float*)d_in[11];
    const float* feat_b      = (const float*)d_in[12];
    const float* wc_W        = (const float*)d_in[13];
    const float* wc_b        = (const float*)d_in[14];
    const float* W_ih        = (const float*)d_in[15];
    const float* W_hh        = (const float*)d_in[16];
    const float* b_ih        = (const float*)d_in[17];
    const float* b_hh        = (const float*)d_in[18];
    float* out = (float*)d_out;

    prep_weights<<<512, 256>>>(td_h_W, hist_W, feat_W, wc_W, W_ih, W_hh, b_ih, b_hh);
    gammah_gemm<<<dim3(BT / 64, Hsz / 64), 256>>>(d, td_h_b);
    alpha_gemm<<<dim3(BT / 64, Fsz / 64), 256>>>(d, m, td_x_W, td_x_b, wc_b);

    rits_persistent<<<NBLK, NTHR>>>(x, m, target_x, target_mask, hist_b, feat_b, out);

    loss_final<<<1, 128>>>(out, out_size);
}

// round 12
// speedup vs baseline: 1.2052x; 1.1608x over previous
#include <cuda_runtime.h>
#include <math.h>

#define Bsz 256
#define Tsz 128
#define Fsz 128
#define Hsz 512
#define BT  (Bsz * Tsz)          // 32768
#define KC  768                  // c_c(128) + h_dec(512) + m(128)
#define N4H 2048                 // 4*H, gate-interleaved
#define NBLK 128                 // persistent grid size
#define NTHR 512

typedef unsigned long long ull;

// ----- device scratch (allocation-free rule: __device__ globals) -----
__device__ __align__(16) float g_h[Bsz * Hsz];
__device__ __align__(16) float g_c[Bsz * Hsz];
__device__ __align__(16) float g_xvec[Bsz * KC];
__device__ __align__(16) float g_xhist[Bsz * Fsz];
__device__ __align__(16) float g_gamma_h[(size_t)BT * Hsz];   // 64 MB
__device__ __align__(16) float g_alpha[BT * Fsz];
__device__ float g_losspart[Tsz * 128];
__device__ float g_maskpart[Tsz * 128];
__device__ __align__(16) float g_tdhT[Fsz * Hsz];
__device__ __align__(16) float g_histT[Hsz * Fsz];            // [k][f]
__device__ __align__(16) float g_featMT[Fsz * Fsz];           // [j][f]
__device__ __align__(16) float g_wcT[2 * Fsz * Fsz];
__device__ __align__(16) float g_WcombT[KC * N4H];
__device__ __align__(16) float g_bcomb[N4H];
__device__ __align__(16) float g_part[(size_t)32 * 4 * 128 * 128];  // P4 split-K partials
__device__ int g_tilecnt[32];            // monotone within a replay

// flag-array grid barrier
__device__ volatile int g_arrive[NBLK];
__device__ volatile int g_release;

__device__ __forceinline__ float fsigmoid(float v) {
    return __fdividef(1.f, 1.f + __expf(-v));
}
__device__ __forceinline__ float tanhap(float x) {
    float r;
    asm("tanh.approx.f32 %0, %1;" : "=f"(r) : "f"(x));
    return r;
}
__device__ __forceinline__ float sigap(float v) {
    return 0.5f * tanhap(0.5f * v) + 0.5f;
}

// ----------------------------------------------------------------------
__global__ void prep_weights(const float* __restrict__ td_h_W,
                             const float* __restrict__ hist_W,
                             const float* __restrict__ feat_W,
                             const float* __restrict__ wc_W,
                             const float* __restrict__ W_ih,
                             const float* __restrict__ W_hh,
                             const float* __restrict__ b_ih,
                             const float* __restrict__ b_hh) {
    int stride = gridDim.x * blockDim.x;
    int tid = blockIdx.x * blockDim.x + threadIdx.x;
    for (int i = tid; i < Fsz * Hsz; i += stride) {
        int k = i / Hsz, n = i % Hsz;
        g_tdhT[i] = td_h_W[n * Fsz + k];
    }
    for (int i = tid; i < Hsz * Fsz; i += stride) {
        int k = i / Fsz, f = i % Fsz;
        g_histT[i] = hist_W[f * Hsz + k];
    }
    for (int i = tid; i < Fsz * Fsz; i += stride) {
        int j = i / Fsz, f = i % Fsz;
        g_featMT[i] = (j == f) ? 0.f : feat_W[f * Fsz + j];
    }
    for (int i = tid; i < 2 * Fsz * Fsz; i += stride) {
        int k = i / Fsz, n = i % Fsz;
        g_wcT[i] = wc_W[n * 2 * Fsz + k];
    }
    for (int i = tid; i < KC * N4H; i += stride) {
        int k = i / N4H, n = i % N4H;
        int j = n >> 2, g = n & 3;
        int row = g * Hsz + j;
        float v;
        if (k < Fsz)            v = W_ih[row * (2 * Fsz) + k];
        else if (k < Fsz + Hsz) v = W_hh[row * Hsz + (k - Fsz)];
        else                    v = W_ih[row * (2 * Fsz) + Fsz + (k - Fsz - Hsz)];
        g_WcombT[i] = v;
    }
    for (int i = tid; i < N4H; i += stride) {
        int j = i >> 2, g = i & 3;
        g_bcomb[i] = b_ih[g * Hsz + j] + b_hh[g * Hsz + j];
    }
}

// ----------------------------------------------------------------------
__global__ void gammah_gemm(const float* __restrict__ d,
                            const float* __restrict__ td_h_b) {
    __shared__ float sA[64][33];
    __shared__ float sB[32][64];
    int m0 = blockIdx.x * 64;
    int n0 = blockIdx.y * 64;
    int tid = threadIdx.x;
    int tx = tid & 15, ty = tid >> 4;
    float acc[4][4] = {};
    for (int kk = 0; kk < Fsz; kk += 32) {
        for (int i = tid; i < 64 * 32; i += 256) {
            int r = i >> 5, k = i & 31;
            sA[r][k] = d[(size_t)(m0 + r) * Fsz + kk + k];
        }
        for (int i = tid; i < 32 * 64; i += 256) {
            int k = i >> 6, n = i & 63;
            sB[k][n] = g_tdhT[(kk + k) * Hsz + n0 + n];
        }
        __syncthreads();
#pragma unroll
        for (int k = 0; k < 32; k++) {
            float a[4], b[4];
#pragma unroll
            for (int i = 0; i < 4; i++) a[i] = sA[ty + i * 16][k];
#pragma unroll
            for (int j = 0; j < 4; j++) b[j] = sB[k][tx + j * 16];
#pragma unroll
            for (int i = 0; i < 4; i++)
#pragma unroll
                for (int j = 0; j < 4; j++) acc[i][j] += a[i] * b[j];
        }
        __syncthreads();
    }
#pragma unroll
    for (int i = 0; i < 4; i++)
#pragma unroll
        for (int j = 0; j < 4; j++) {
            int n = n0 + tx + j * 16;
            int row = m0 + ty + i * 16;
            g_gamma_h[(size_t)row * Hsz + n] = __expf(-fmaxf(acc[i][j] + td_h_b[n], 0.f));
        }
}

// ----------------------------------------------------------------------
__global__ void alpha_gemm(const float* __restrict__ d,
                           const float* __restrict__ m,
                           const float* __restrict__ td_x_W,
                           const float* __restrict__ td_x_b,
                           const float* __restrict__ wc_b) {
    __shared__ float sA[64][33];
    __shared__ float sB[32][64];
    int m0 = blockIdx.x * 64;
    int n0 = blockIdx.y * 64;
    int tid = threadIdx.x;
    int tx = tid & 15, ty = tid >> 4;
    float acc[4][4] = {};
    for (int kk = 0; kk < 2 * Fsz; kk += 32) {
        for (int i = tid; i < 64 * 32; i += 256) {
            int r = i >> 5, k = i & 31;
            int kg = kk + k;
            float v;
            if (kg < Fsz) {
                float dv = d[(size_t)(m0 + r) * Fsz + kg];
                float u = dv * td_x_W[kg * Fsz + kg] + td_x_b[kg];
                v = __expf(-fmaxf(u, 0.f));
            } else {
                v = m[(size_t)(m0 + r) * Fsz + (kg - Fsz)];
            }
            sA[r][k] = v;
        }
        for (int i = tid; i < 32 * 64; i += 256) {
            int k = i >> 6, n = i & 63;
            sB[k][n] = g_wcT[(kk + k) * Fsz + n0 + n];
        }
        __syncthreads();
#pragma unroll
        for (int k = 0; k < 32; k++) {
            float a[4], b[4];
#pragma unroll
            for (int i = 0; i < 4; i++) a[i] = sA[ty + i * 16][k];
#pragma unroll
            for (int j = 0; j < 4; j++) b[j] = sB[k][tx + j * 16];
#pragma unroll
            for (int i = 0; i < 4; i++)
#pragma unroll
                for (int j = 0; j < 4; j++) acc[i][j] += a[i] * b[j];
        }
        __syncthreads();
    }
#pragma unroll
    for (int i = 0; i < 4; i++)
#pragma unroll
        for (int j = 0; j < 4; j++) {
            int n = n0 + tx + j * 16;
            int row = m0 + ty + i * 16;
            float v = acc[i][j] + wc_b[n];
            g_alpha[row * Fsz + n] = fsigmoid(v);
        }
}

// ======================================================================
#define FMA2(acc, a2, b2) \
    asm("fma.rn.f32x2 %0, %1, %2, %0;" : "+l"(acc) : "l"(a2), "l"(b2))
#define DUP32(d, s) \
    asm("mov.b64 %0, {%1, %1};" : "=l"(d) : "r"(s))
#define UNPACK2(lo, hi, in) \
    asm("mov.b64 {%0, %1}, %2;" : "=f"(lo), "=f"(hi) : "l"(in))

// flag-array barrier: one STG per block, block 0 gathers, no atomic contention
__device__ __forceinline__ void grid_sync(int& gen) {
    gen++;
    __threadfence();
    __syncthreads();
    if (blockIdx.x == 0) {
        int tid = threadIdx.x;
        if (tid > 0 && tid < NBLK) {
            while (g_arrive[tid] - gen < 0) { }
        }
        __syncthreads();
        if (tid == 0) g_release = gen;
    } else {
        if (threadIdx.x == 0) {
            g_arrive[blockIdx.x] = gen;
            while (g_release - gen < 0) { }
        }
    }
    __syncthreads();
    __threadfence();
}

// dynamic smem layout (floats):
//  [0, 24576)          sBres  [192][128]  P4 B tile, resident across all t
//  [24576, 40960)      sHist  [512][32]   histT col-slice, resident
//  [40960, 45056)      sFeat  [128][32]   featMT col-slice, resident
//  [45056, 54272)      working:
//     P4: sA double buffer 2 x [128][36] = 9216
//     A:  sh [8][512]=4096 | sxc [8][132]=1056 @+4096 | spartU ull[512] @+5152(f)
//         sred[16] @+6176 | sred2[16] @+6192
#define OFF_HIST 24576
#define OFF_FEAT 40960
#define OFF_WORK 45056
#define SMEM_FLOATS 54272
#define SMEM_BYTES (SMEM_FLOATS * 4)

__global__ void __launch_bounds__(NTHR, 1)
rits_persistent(const float* __restrict__ x,
                const float* __restrict__ m,
                const float* __restrict__ target_x,
                const float* __restrict__ target_mask,
                const float* __restrict__ hist_b,
                const float* __restrict__ feat_b,
                float* __restrict__ out) {
    extern __shared__ __align__(16) float smem[];
    float* sBres = smem;
    float* sHist = smem + OFF_HIST;
    float* sFeat = smem + OFF_FEAT;
    float* sA    = smem + OFF_WORK;          // 2 x [128][36]
    float* sh    = smem + OFF_WORK;          // [8][512]
    float* sxc   = smem + OFF_WORK + 4096;   // [8][132]
    ull*   spartU = reinterpret_cast<ull*>(smem + OFF_WORK + 5152);  // [512]
    float* sred  = smem + OFF_WORK + 6176;
    float* sred2 = smem + OFF_WORK + 6192;

    const int tid = threadIdx.x;
    const int bid = blockIdx.x;

    int gen = g_release;

    // init state (+ reset counters each replay)
    for (int i = bid * NTHR + tid; i < Bsz * Hsz; i += NBLK * NTHR) {
        g_h[i] = 0.f; g_c[i] = 0.f;
    }
    if (bid == 0 && tid < 32) g_tilecnt[tid] = 0;

    // phase A decode: block = (row-group r8 of 8 rows) x (col-group cg of 32 cols)
    const int r8 = bid >> 2, cg = bid & 3;
    const int rows8 = r8 * 8;
    const int f2 = tid & 15;                // f-pair within col-group
    const int rloc = (tid >> 4) & 7;        // local row 0..7
    const int ksA = tid >> 7;               // 4-way k split

    // P4 decode: 32 tiles (2 row x 16 col of 128x128) x 4-way K-split (192)
    const int ks4  = bid & 3;
    const int tile4 = bid >> 2;
    const int b0B = (tile4 >> 4) * 128;
    const int n0_4 = (tile4 & 15) * 128;
    const int k0b = ks4 * 192;
    const int ty4 = tid >> 4, tx4 = tid & 15;

    // -------- load resident weights once --------
#pragma unroll
    for (int q = 0; q < 12; q++) {          // sBres: 6144 f4
        int idx = tid + q * NTHR;
        int kk = idx >> 5, nq = idx & 31;
        *reinterpret_cast<float4*>(&sBres[kk * 128 + nq * 4]) =
            *reinterpret_cast<const float4*>(
                &g_WcombT[(size_t)(k0b + kk) * N4H + n0_4 + nq * 4]);
    }
#pragma unroll
    for (int q = 0; q < 8; q++) {           // sHist: 4096 f4
        int idx = tid + q * NTHR;
        int k = idx >> 3, fq = idx & 7;
        *reinterpret_cast<float4*>(&sHist[k * 32 + fq * 4]) =
            *reinterpret_cast<const float4*>(
                &g_histT[k * Fsz + cg * 32 + fq * 4]);
    }
#pragma unroll
    for (int q = 0; q < 2; q++) {           // sFeat: 1024 f4
        int idx = tid + q * NTHR;
        int j = idx >> 3, fq = idx & 7;
        *reinterpret_cast<float4*>(&sFeat[j * 32 + fq * 4]) =
            *reinterpret_cast<const float4*>(
                &g_featMT[j * Fsz + cg * 32 + fq * 4]);
    }
    grid_sync(gen);

#pragma unroll 1
    for (int t = 0; t < Tsz; t++) {
        // ================= A1: x_hist col-slice GEMM (resident histT) =================
        {
            // h_dec for 8 rows -> sh (+ xvec from col-group 0)
#pragma unroll
            for (int q = 0; q < 2; q++) {
                int idx = tid + q * NTHR;       // 0..1023 f4
                int r = idx >> 7, kq = idx & 127;
                const float4 h4 = *reinterpret_cast<const float4*>(
                    &g_h[(rows8 + r) * Hsz + kq * 4]);
                const float4 g4 = *reinterpret_cast<const float4*>(
                    &g_gamma_h[((size_t)(rows8 + r) * Tsz + t) * Hsz + kq * 4]);
                float4 o;
                o.x = h4.x * g4.x; o.y = h4.y * g4.y;
                o.z = h4.z * g4.z; o.w = h4.w * g4.w;
                *reinterpret_cast<float4*>(&sh[r * 512 + kq * 4]) = o;
                if (cg == 0)
                    *reinterpret_cast<float4*>(
                        &g_xvec[(rows8 + r) * KC + Fsz + kq * 4]) = o;
            }
            __syncthreads();

            ull acc = 0ull;
            const float* hr = sh + rloc * 512 + ksA * 128;
            const float* wp = sHist + ksA * 128 * 32 + f2 * 2;
#pragma unroll 8
            for (int k = 0; k < 128; k++) {
                ull b2 = *reinterpret_cast<const ull*>(&wp[k * 32]);
                ull ad;
                DUP32(ad, __float_as_uint(hr[k]));
                FMA2(acc, ad, b2);
            }
            spartU[tid] = acc;
            __syncthreads();
            if (tid < 128) {
                float s0 = 0.f, s1 = 0.f;
#pragma unroll
                for (int p = 0; p < 4; p++) {
                    float lo, hi;
                    UNPACK2(lo, hi, spartU[tid + p * 128]);
                    s0 += lo; s1 += hi;
                }
                int f = cg * 32 + f2 * 2;
                g_xhist[(rows8 + rloc) * Fsz + f]     = s0 + hist_b[f];
                g_xhist[(rows8 + rloc) * Fsz + f + 1] = s1 + hist_b[f + 1];
            }
        }
        grid_sync(gen);

        // ================= A2: z_h col-slice + elementwise + loss =================
        {
            if (tid < 256) {                    // x_c: 256 f4 cells (8 rows x 128 j)
                int r = tid >> 5, jq = tid & 31;
                size_t base = ((size_t)(rows8 + r) * Tsz + t) * Fsz + jq * 4;
                float4 mv = *reinterpret_cast<const float4*>(&m[base]);
                float4 xv = *reinterpret_cast<const float4*>(&x[base]);
                float4 xh = *reinterpret_cast<const float4*>(
                    &g_xhist[(rows8 + r) * Fsz + jq * 4]);
                float4 o;
                o.x = mv.x * xv.x + (1.f - mv.x) * xh.x;
                o.y = mv.y * xv.y + (1.f - mv.y) * xh.y;
                o.z = mv.z * xv.z + (1.f - mv.z) * xh.z;
                o.w = mv.w * xv.w + (1.f - mv.w) * xh.w;
                *reinterpret_cast<float4*>(&sxc[r * 132 + jq * 4]) = o;
            }
            __syncthreads();

            ull accz = 0ull;
            const float* cr = sxc + rloc * 132 + ksA * 32;
            const float* fp = sFeat + ksA * 32 * 32 + f2 * 2;
#pragma unroll 8
            for (int j = 0; j < 32; j++) {
                ull b2 = *reinterpret_cast<const ull*>(&fp[j * 32]);
                ull ad;
                DUP32(ad, __float_as_uint(cr[j]));
                FMA2(accz, ad, b2);
            }
            spartU[tid] = accz;
            __syncthreads();

            float lp = 0.f, es = 0.f;
            if (tid < 128) {
                float z0 = 0.f, z1 = 0.f;
#pragma unroll
                for (int p = 0; p < 4; p++) {
                    float lo, hi;
                    UNPACK2(lo, hi, spartU[tid + p * 128]);
                    z0 += lo; z1 += hi;
                }
                int f = cg * 32 + f2 * 2;
                int r = rows8 + rloc;
                size_t base = ((size_t)r * Tsz + t) * Fsz + f;
                float zz[2] = { z0 + feat_b[f], z1 + feat_b[f + 1] };
#pragma unroll
                for (int c = 0; c < 2; c++) {
                    float xh = g_xhist[r * Fsz + f + c];
                    float a = g_alpha[base + c];
                    float mv = m[base + c], xv = x[base + c];
                    float ch = a * zz[c] + (1.f - a) * xh;
                    float cc = mv * xv + (1.f - mv) * ch;
                    g_xvec[r * KC + f + c] = cc;
                    g_xvec[r * KC + (Fsz + Hsz) + f + c] = mv;
                    out[base + c] = cc;
                    float ev = target_mask[base + c];
                    float tg = target_x[base + c];
                    float d1 = xh - tg, d2 = zz[c] - tg, d3 = ch - tg;
                    lp += ev * (d1 * d1 + d2 * d2 + d3 * d3);
                    es += ev;
                }
            }
            for (int o = 16; o; o >>= 1) {
                lp += __shfl_down_sync(0xffffffffu, lp, o);
                es += __shfl_down_sync(0xffffffffu, es, o);
            }
            if ((tid & 31) == 0) { sred[tid >> 5] = lp; sred2[tid >> 5] = es; }
            __syncthreads();
            if (tid == 0) {
                float tot = 0.f, tot2 = 0.f;
                for (int i = 0; i < 16; i++) { tot += sred[i]; tot2 += sred2[i]; }
                g_losspart[t * 128 + bid] = tot;
                g_maskpart[t * 128 + bid] = tot2;
            }
        }
        grid_sync(gen);

        // ===== P4: gate GEMM 128x128x192 split-K, B resident, micro 4x8 =====
        {
            ull acc[4][4];
#pragma unroll
            for (int i = 0; i < 4; i++)
#pragma unroll
                for (int j = 0; j < 4; j++) acc[i][j] = 0ull;

            float4 pa[2];
#pragma unroll
            for (int q = 0; q < 2; q++) {
                int i = tid + q * NTHR;
                int mm = i >> 3, kq = i & 7;
                pa[q] = *reinterpret_cast<const float4*>(
                    &g_xvec[(b0B + mm) * KC + k0b + kq * 4]);
            }

#pragma unroll 1
            for (int kb = 0; kb < 6; kb++) {
                float* sAc = sA + (kb & 1) * 4608;
#pragma unroll
                for (int q = 0; q < 2; q++) {
                    int i = tid + q * NTHR;
                    int mm = i >> 3, kq = i & 7;
                    *reinterpret_cast<float4*>(&sAc[mm * 36 + kq * 4]) = pa[q];
                }
                __syncthreads();
                if (kb < 5) {
                    const int k0n = k0b + (kb + 1) * 32;
#pragma unroll
                    for (int q = 0; q < 2; q++) {
                        int i = tid + q * NTHR;
                        int mm = i >> 3, kq = i & 7;
                        pa[q] = *reinterpret_cast<const float4*>(
                            &g_xvec[(b0B + mm) * KC + k0n + kq * 4]);
                    }
                }
                const float* sBk = sBres + kb * 32 * 128;
#pragma unroll 8
                for (int k = 0; k < 32; k++) {
                    ulonglong2 bb0 = *reinterpret_cast<const ulonglong2*>(
                        &sBk[k * 128 + tx4 * 8]);
                    ulonglong2 bb1 = *reinterpret_cast<const ulonglong2*>(
                        &sBk[k * 128 + tx4 * 8 + 4]);
#pragma unroll
                    for (int r2 = 0; r2 < 4; r2++) {
                        ull ad;
                        DUP32(ad, __float_as_uint(sAc[(ty4 * 4 + r2) * 36 + k]));
                        FMA2(acc[r2][0], ad, bb0.x);
                        FMA2(acc[r2][1], ad, bb0.y);
                        FMA2(acc[r2][2], ad, bb1.x);
                        FMA2(acc[r2][3], ad, bb1.y);
                    }
                }
            }

            // store partials
            size_t pbase = (size_t)(tile4 * 4 + ks4) * 16384;
#pragma unroll
            for (int r2 = 0; r2 < 4; r2++) {
#pragma unroll
                for (int cp = 0; cp < 4; cp++) {
                    size_t off = pbase + (size_t)(ty4 * 4 + r2) * 128 + tx4 * 8 + cp * 2;
                    *reinterpret_cast<ull*>(&g_part[off]) = acc[r2][cp];
                }
            }
            __threadfence();
            __syncthreads();
            if (tid == 0) {
                atomicAdd(&g_tilecnt[tile4], 1);
                while (*(volatile int*)&g_tilecnt[tile4] - 4 * (t + 1) < 0) { }
            }
            __syncthreads();
            __threadfence();   // acquire

            // even epilogue: each K-block handles its 32-row quarter of the tile
            size_t tb = (size_t)tile4 * 4 * 16384;
            float4 bc = *reinterpret_cast<const float4*>(&g_bcomb[n0_4 + (tid & 31) * 4]);
#pragma unroll
            for (int q = 0; q < 2; q++) {
                int idx = tid + q * NTHR;        // 0..1023 f4-cells
                int row = ks4 * 32 + (idx >> 5), u = idx & 31;
                size_t go_off = (size_t)row * 128 + u * 4;
                float4 p0 = *reinterpret_cast<const float4*>(&g_part[tb + go_off]);
                float4 p1 = *reinterpret_cast<const float4*>(&g_part[tb + 16384 + go_off]);
                float4 p2 = *reinterpret_cast<const float4*>(&g_part[tb + 32768 + go_off]);
                float4 p3 = *reinterpret_cast<const float4*>(&g_part[tb + 49152 + go_off]);
                float gi = ((p0.x + p1.x) + (p2.x + p3.x)) + bc.x;
                float gf = ((p0.y + p1.y) + (p2.y + p3.y)) + bc.y;
                float gg = ((p0.z + p1.z) + (p2.z + p3.z)) + bc.z;
                float gO = ((p0.w + p1.w) + (p2.w + p3.w)) + bc.w;
                float si = sigap(gi);
                float sf = sigap(gf);
                float so = sigap(gO);
                float tg = tanhap(gg);
                int b = b0B + row;
                int j = (n0_4 >> 2) + u;
                float cn = sf * g_c[b * Hsz + j] + si * tg;
                g_c[b * Hsz + j] = cn;
                g_h[b * Hsz + j] = so * tanhap(cn);
            }
        }
        grid_sync(gen);
    }
}

// ----------------------------------------------------------------------
__global__ void loss_final(float* __restrict__ out, int out_size) {
    __shared__ float s[128];
    int t = threadIdx.x;
    float v = 0.f, mv = 0.f;
    for (int p = 0; p < 128; p++) {
        v += g_losspart[t * 128 + p];
        mv += g_maskpart[t * 128 + p];
    }
    s[t] = v / (mv + 1e-8f);
    __syncthreads();
    if (t == 0) {
        float tot = 0.f;
        for (int i = 0; i < 128; i++) tot += s[i];
        out[out_size - 1] = tot / (float)Tsz;
    }
}

// ----------------------------------------------------------------------
extern "C" void kernel_launch(void* const* d_in, const int* in_sizes, int n_in,
                              void* d_out, int out_size) {
    const float* x           = (const float*)d_in[0];
    const float* m           = (const float*)d_in[1];
    const float* d           = (const float*)d_in[2];
    const float* target_x    = (const float*)d_in[3];
    const float* target_mask = (const float*)d_in[4];
    const float* td_h_W      = (const float*)d_in[5];
    const float* td_h_b      = (const float*)d_in[6];
    const float* td_x_W      = (const float*)d_in[7];
    const float* td_x_b      = (const float*)d_in[8];
    const float* hist_W      = (const float*)d_in[9];
    const float* hist_b      = (const float*)d_in[10];
    const float* feat_W      = (const float*)d_in[11];
    const float* feat_b      = (const float*)d_in[12];
    const float* wc_W        = (const float*)d_in[13];
    const float* wc_b        = (const float*)d_in[14];
    const float* W_ih        = (const float*)d_in[15];
    const float* W_hh        = (const float*)d_in[16];
    const float* b_ih        = (const float*)d_in[17];
    const float* b_hh        = (const float*)d_in[18];
    float* out = (float*)d_out;

    cudaFuncSetAttribute(rits_persistent,
                         cudaFuncAttributeMaxDynamicSharedMemorySize, SMEM_BYTES);

    prep_weights<<<512, 256>>>(td_h_W, hist_W, feat_W, wc_W, W_ih, W_hh, b_ih, b_hh);
    gammah_gemm<<<dim3(BT / 64, Hsz / 64), 256>>>(d, td_h_b);
    alpha_gemm<<<dim3(BT / 64, Fsz / 64), 256>>>(d, m, td_x_W, td_x_b, wc_b);

    rits_persistent<<<NBLK, NTHR, SMEM_BYTES>>>(x, m, target_x, target_mask,
                                                hist_b, feat_b, out);

    loss_final<<<1, 128>>>(out, out_size);
}

// round 13
// speedup vs baseline: 1.2521x; 1.0389x over previous
#include <cuda_runtime.h>
#include <math.h>

#define Bsz 256
#define Tsz 128
#define Fsz 128
#define Hsz 512
#define BT  (Bsz * Tsz)          // 32768
#define KC  768                  // c_c(128) + h_dec(512) + m(128)
#define N4H 2048                 // 4*H, gate-interleaved
#define NBLK 128                 // persistent grid size
#define NTHR 512

typedef unsigned long long ull;

// ----- device scratch (allocation-free rule: __device__ globals) -----
__device__ __align__(16) float g_h[Bsz * Hsz];
__device__ __align__(16) float g_c[Bsz * Hsz];
__device__ __align__(16) float g_xvec[Bsz * KC];
__device__ __align__(16) float g_xhist[Bsz * Fsz];
__device__ __align__(16) float g_gamma_h[(size_t)BT * Hsz];   // 64 MB
__device__ __align__(16) float g_alpha[BT * Fsz];
__device__ float g_losspart[Tsz * 128];
__device__ float g_maskpart[Tsz * 128];
__device__ __align__(16) float g_tdhT[Fsz * Hsz];
__device__ __align__(16) float g_histT[Hsz * Fsz];            // [k][f]
__device__ __align__(16) float g_featMT[Fsz * Fsz];           // [j][f]
__device__ __align__(16) float g_wcT[2 * Fsz * Fsz];
__device__ __align__(16) float g_WcombT[KC * N4H];
__device__ __align__(16) float g_bcomb[N4H];
__device__ __align__(16) float g_part[(size_t)32 * 4 * 128 * 128];  // P4 split-K partials

// dataflow counters (monotone within a replay; reset in init)
__device__ int g_fxh[32];      // A1 arrivals per 8-row group (target 4(t+1))
__device__ int g_fa2[32];      // A2 arrivals per 8-row group (target 4(t+1))
__device__ int g_fh[8];        // P4 epilogue arrivals per 32-row h group (target 16(t+1))
__device__ int g_tilecnt[32];  // P4 per-tile K-split gate (target 4(t+1))

// flag-array grid barrier (init only)
__device__ volatile int g_arrive[NBLK];
__device__ volatile int g_release;

__device__ __forceinline__ float fsigmoid(float v) {
    return __fdividef(1.f, 1.f + __expf(-v));
}
__device__ __forceinline__ float tanhap(float x) {
    float r;
    asm("tanh.approx.f32 %0, %1;" : "=f"(r) : "f"(x));
    return r;
}
__device__ __forceinline__ float sigap(float v) {
    return 0.5f * tanhap(0.5f * v) + 0.5f;
}

// ----------------------------------------------------------------------
__global__ void prep_weights(const float* __restrict__ td_h_W,
                             const float* __restrict__ hist_W,
                             const float* __restrict__ feat_W,
                             const float* __restrict__ wc_W,
                             const float* __restrict__ W_ih,
                             const float* __restrict__ W_hh,
                             const float* __restrict__ b_ih,
                             const float* __restrict__ b_hh) {
    int stride = gridDim.x * blockDim.x;
    int tid = blockIdx.x * blockDim.x + threadIdx.x;
    for (int i = tid; i < Fsz * Hsz; i += stride) {
        int k = i / Hsz, n = i % Hsz;
        g_tdhT[i] = td_h_W[n * Fsz + k];
    }
    for (int i = tid; i < Hsz * Fsz; i += stride) {
        int k = i / Fsz, f = i % Fsz;
        g_histT[i] = hist_W[f * Hsz + k];
    }
    for (int i = tid; i < Fsz * Fsz; i += stride) {
        int j = i / Fsz, f = i % Fsz;
        g_featMT[i] = (j == f) ? 0.f : feat_W[f * Fsz + j];
    }
    for (int i = tid; i < 2 * Fsz * Fsz; i += stride) {
        int k = i / Fsz, n = i % Fsz;
        g_wcT[i] = wc_W[n * 2 * Fsz + k];
    }
    for (int i = tid; i < KC * N4H; i += stride) {
        int k = i / N4H, n = i % N4H;
        int j = n >> 2, g = n & 3;
        int row = g * Hsz + j;
        float v;
        if (k < Fsz)            v = W_ih[row * (2 * Fsz) + k];
        else if (k < Fsz + Hsz) v = W_hh[row * Hsz + (k - Fsz)];
        else                    v = W_ih[row * (2 * Fsz) + Fsz + (k - Fsz - Hsz)];
        g_WcombT[i] = v;
    }
    for (int i = tid; i < N4H; i += stride) {
        int j = i >> 2, g = i & 3;
        g_bcomb[i] = b_ih[g * Hsz + j] + b_hh[g * Hsz + j];
    }
}

// ----------------------------------------------------------------------
__global__ void gammah_gemm(const float* __restrict__ d,
                            const float* __restrict__ td_h_b) {
    __shared__ float sA[64][33];
    __shared__ float sB[32][64];
    int m0 = blockIdx.x * 64;
    int n0 = blockIdx.y * 64;
    int tid = threadIdx.x;
    int tx = tid & 15, ty = tid >> 4;
    float acc[4][4] = {};
    for (int kk = 0; kk < Fsz; kk += 32) {
        for (int i = tid; i < 64 * 32; i += 256) {
            int r = i >> 5, k = i & 31;
            sA[r][k] = d[(size_t)(m0 + r) * Fsz + kk + k];
        }
        for (int i = tid; i < 32 * 64; i += 256) {
            int k = i >> 6, n = i & 63;
            sB[k][n] = g_tdhT[(kk + k) * Hsz + n0 + n];
        }
        __syncthreads();
#pragma unroll
        for (int k = 0; k < 32; k++) {
            float a[4], b[4];
#pragma unroll
            for (int i = 0; i < 4; i++) a[i] = sA[ty + i * 16][k];
#pragma unroll
            for (int j = 0; j < 4; j++) b[j] = sB[k][tx + j * 16];
#pragma unroll
            for (int i = 0; i < 4; i++)
#pragma unroll
                for (int j = 0; j < 4; j++) acc[i][j] += a[i] * b[j];
        }
        __syncthreads();
    }
#pragma unroll
    for (int i = 0; i < 4; i++)
#pragma unroll
        for (int j = 0; j < 4; j++) {
            int n = n0 + tx + j * 16;
            int row = m0 + ty + i * 16;
            g_gamma_h[(size_t)row * Hsz + n] = __expf(-fmaxf(acc[i][j] + td_h_b[n], 0.f));
        }
}

// ----------------------------------------------------------------------
__global__ void alpha_gemm(const float* __restrict__ d,
                           const float* __restrict__ m,
                           const float* __restrict__ td_x_W,
                           const float* __restrict__ td_x_b,
                           const float* __restrict__ wc_b) {
    __shared__ float sA[64][33];
    __shared__ float sB[32][64];
    int m0 = blockIdx.x * 64;
    int n0 = blockIdx.y * 64;
    int tid = threadIdx.x;
    int tx = tid & 15, ty = tid >> 4;
    float acc[4][4] = {};
    for (int kk = 0; kk < 2 * Fsz; kk += 32) {
        for (int i = tid; i < 64 * 32; i += 256) {
            int r = i >> 5, k = i & 31;
            int kg = kk + k;
            float v;
            if (kg < Fsz) {
                float dv = d[(size_t)(m0 + r) * Fsz + kg];
                float u = dv * td_x_W[kg * Fsz + kg] + td_x_b[kg];
                v = __expf(-fmaxf(u, 0.f));
            } else {
                v = m[(size_t)(m0 + r) * Fsz + (kg - Fsz)];
            }
            sA[r][k] = v;
        }
        for (int i = tid; i < 32 * 64; i += 256) {
            int k = i >> 6, n = i & 63;
            sB[k][n] = g_wcT[(kk + k) * Fsz + n0 + n];
        }
        __syncthreads();
#pragma unroll
        for (int k = 0; k < 32; k++) {
            float a[4], b[4];
#pragma unroll
            for (int i = 0; i < 4; i++) a[i] = sA[ty + i * 16][k];
#pragma unroll
            for (int j = 0; j < 4; j++) b[j] = sB[k][tx + j * 16];
#pragma unroll
            for (int i = 0; i < 4; i++)
#pragma unroll
                for (int j = 0; j < 4; j++) acc[i][j] += a[i] * b[j];
        }
        __syncthreads();
    }
#pragma unroll
    for (int i = 0; i < 4; i++)
#pragma unroll
        for (int j = 0; j < 4; j++) {
            int n = n0 + tx + j * 16;
            int row = m0 + ty + i * 16;
            float v = acc[i][j] + wc_b[n];
            g_alpha[row * Fsz + n] = fsigmoid(v);
        }
}

// ======================================================================
#define FMA2(acc, a2, b2) \
    asm("fma.rn.f32x2 %0, %1, %2, %0;" : "+l"(acc) : "l"(a2), "l"(b2))
#define DUP32(d, s) \
    asm("mov.b64 %0, {%1, %1};" : "=l"(d) : "r"(s))
#define UNPACK2(lo, hi, in) \
    asm("mov.b64 {%0, %1}, %2;" : "=f"(lo), "=f"(hi) : "l"(in))

// flag-array barrier (init only)
__device__ __forceinline__ void grid_sync(int& gen) {
    gen++;
    __threadfence();
    __syncthreads();
    if (blockIdx.x == 0) {
        int tid = threadIdx.x;
        if (tid > 0 && tid < NBLK) {
            while (g_arrive[tid] - gen < 0) { }
        }
        __syncthreads();
        if (tid == 0) g_release = gen;
    } else {
        if (threadIdx.x == 0) {
            g_arrive[blockIdx.x] = gen;
            while (g_release - gen < 0) { }
        }
    }
    __syncthreads();
    __threadfence();
}

// dynamic smem layout (floats):
//  [0, 24576)          sBres  [192][128]  P4 B tile, resident across all t
//  [24576, 40960)      sHist  [512][32]   histT col-slice, resident
//  [40960, 45056)      sFeat  [128][32]   featMT col-slice, resident
//  [45056, 54272)      working (P4 double-buffer sA / phase-A buffers)
#define OFF_HIST 24576
#define OFF_FEAT 40960
#define OFF_WORK 45056
#define SMEM_FLOATS 54272
#define SMEM_BYTES (SMEM_FLOATS * 4)

__global__ void __launch_bounds__(NTHR, 1)
rits_persistent(const float* __restrict__ x,
                const float* __restrict__ m,
                const float* __restrict__ target_x,
                const float* __restrict__ target_mask,
                const float* __restrict__ hist_b,
                const float* __restrict__ feat_b,
                float* __restrict__ out) {
    extern __shared__ __align__(16) float smem[];
    float* sBres = smem;
    float* sHist = smem + OFF_HIST;
    float* sFeat = smem + OFF_FEAT;
    float* sA    = smem + OFF_WORK;          // 2 x [128][36]
    float* sh    = smem + OFF_WORK;          // [8][512]
    float* sxc   = smem + OFF_WORK + 4096;   // [8][132]
    ull*   spartU = reinterpret_cast<ull*>(smem + OFF_WORK + 5152);  // [512]
    float* sred  = smem + OFF_WORK + 6176;
    float* sred2 = smem + OFF_WORK + 6192;

    const int tid = threadIdx.x;
    const int bid = blockIdx.x;

    int gen = g_release;

    // init state + reset all dataflow counters each replay
    for (int i = bid * NTHR + tid; i < Bsz * Hsz; i += NBLK * NTHR) {
        g_h[i] = 0.f; g_c[i] = 0.f;
    }
    if (bid == 0 && tid < 32) {
        g_fxh[tid] = 0;
        g_fa2[tid] = 0;
        g_tilecnt[tid] = 0;
        if (tid < 8) g_fh[tid] = 0;
    }

    // phase A decode: block = (row-group r8 of 8 rows) x (col-group cg of 32 cols)
    const int r8 = bid >> 2, cg = bid & 3;
    const int rows8 = r8 * 8;
    const int f2 = tid & 15;                // f-pair within col-group
    const int rloc = (tid >> 4) & 7;        // local row 0..7
    const int ksA = tid >> 7;               // 4-way k split

    // P4 decode: 32 tiles (2 row x 16 col of 128x128) x 4-way K-split (192)
    const int ks4  = bid & 3;
    const int tile4 = bid >> 2;
    const int b0B = (tile4 >> 4) * 128;
    const int n0_4 = (tile4 & 15) * 128;
    const int k0b = ks4 * 192;
    const int ty4 = tid >> 4, tx4 = tid & 15;

    // -------- load resident weights once --------
#pragma unroll
    for (int q = 0; q < 12; q++) {          // sBres: 6144 f4
        int idx = tid + q * NTHR;
        int kk = idx >> 5, nq = idx & 31;
        *reinterpret_cast<float4*>(&sBres[kk * 128 + nq * 4]) =
            *reinterpret_cast<const float4*>(
                &g_WcombT[(size_t)(k0b + kk) * N4H + n0_4 + nq * 4]);
    }
#pragma unroll
    for (int q = 0; q < 8; q++) {           // sHist: 4096 f4
        int idx = tid + q * NTHR;
        int k = idx >> 3, fq = idx & 7;
        *reinterpret_cast<float4*>(&sHist[k * 32 + fq * 4]) =
            *reinterpret_cast<const float4*>(
                &g_histT[k * Fsz + cg * 32 + fq * 4]);
    }
#pragma unroll
    for (int q = 0; q < 2; q++) {           // sFeat: 1024 f4
        int idx = tid + q * NTHR;
        int j = idx >> 3, fq = idx & 7;
        *reinterpret_cast<float4*>(&sFeat[j * 32 + fq * 4]) =
            *reinterpret_cast<const float4*>(
                &g_featMT[j * Fsz + cg * 32 + fq * 4]);
    }
    grid_sync(gen);   // counters reset + h/c zero + residents loaded

#pragma unroll 1
    for (int t = 0; t < Tsz; t++) {
        // ================= A1: x_hist col-slice GEMM (resident histT) =================
        {
            // wait for h(t) of our 32-row group (written by 16 P4 blocks of step t-1)
            if (t > 0) {
                if (tid == 0) {
                    while (*(volatile int*)&g_fh[r8 >> 2] < 16 * t) { }
                    __threadfence();
                }
                __syncthreads();
            }

            // h_dec for 8 rows -> sh (+ xvec from col-group 0)
#pragma unroll
            for (int q = 0; q < 2; q++) {
                int idx = tid + q * NTHR;       // 0..1023 f4
                int r = idx >> 7, kq = idx & 127;
                const float4 h4 = *reinterpret_cast<const float4*>(
                    &g_h[(rows8 + r) * Hsz + kq * 4]);
                const float4 g4 = *reinterpret_cast<const float4*>(
                    &g_gamma_h[((size_t)(rows8 + r) * Tsz + t) * Hsz + kq * 4]);
                float4 o;
                o.x = h4.x * g4.x; o.y = h4.y * g4.y;
                o.z = h4.z * g4.z; o.w = h4.w * g4.w;
                *reinterpret_cast<float4*>(&sh[r * 512 + kq * 4]) = o;
                if (cg == 0)
                    *reinterpret_cast<float4*>(
                        &g_xvec[(rows8 + r) * KC + Fsz + kq * 4]) = o;
            }
            __syncthreads();

            ull acc = 0ull;
            const float* hr = sh + rloc * 512 + ksA * 128;
            const float* wp = sHist + ksA * 128 * 32 + f2 * 2;
#pragma unroll 8
            for (int k = 0; k < 128; k++) {
                ull b2 = *reinterpret_cast<const ull*>(&wp[k * 32]);
                ull ad;
                DUP32(ad, __float_as_uint(hr[k]));
                FMA2(acc, ad, b2);
            }
            spartU[tid] = acc;
            __syncthreads();
            if (tid < 128) {
                float s0 = 0.f, s1 = 0.f;
#pragma unroll
                for (int p = 0; p < 4; p++) {
                    float lo, hi;
                    UNPACK2(lo, hi, spartU[tid + p * 128]);
                    s0 += lo; s1 += hi;
                }
                int f = cg * 32 + f2 * 2;
                g_xhist[(rows8 + rloc) * Fsz + f]     = s0 + hist_b[f];
                g_xhist[(rows8 + rloc) * Fsz + f + 1] = s1 + hist_b[f + 1];
            }
            __threadfence();
            __syncthreads();
            if (tid == 0) atomicAdd(&g_fxh[r8], 1);
        }

        // ================= A2: z_h col-slice + elementwise + loss =================
        {
            // wait for full x_hist rows (4 col-blocks of our row-group)
            if (tid == 0) {
                while (*(volatile int*)&g_fxh[r8] < 4 * (t + 1)) { }
                __threadfence();
            }
            __syncthreads();

            if (tid < 256) {                    // x_c: 256 f4 cells (8 rows x 128 j)
                int r = tid >> 5, jq = tid & 31;
                size_t base = ((size_t)(rows8 + r) * Tsz + t) * Fsz + jq * 4;
                float4 mv = *reinterpret_cast<const float4*>(&m[base]);
                float4 xv = *reinterpret_cast<const float4*>(&x[base]);
                float4 xh = *reinterpret_cast<const float4*>(
                    &g_xhist[(rows8 + r) * Fsz + jq * 4]);
                float4 o;
                o.x = mv.x * xv.x + (1.f - mv.x) * xh.x;
                o.y = mv.y * xv.y + (1.f - mv.y) * xh.y;
                o.z = mv.z * xv.z + (1.f - mv.z) * xh.z;
                o.w = mv.w * xv.w + (1.f - mv.w) * xh.w;
                *reinterpret_cast<float4*>(&sxc[r * 132 + jq * 4]) = o;
            }
            __syncthreads();

            ull accz = 0ull;
            const float* cr = sxc + rloc * 132 + ksA * 32;
            const float* fp = sFeat + ksA * 32 * 32 + f2 * 2;
#pragma unroll 8
            for (int j = 0; j < 32; j++) {
                ull b2 = *reinterpret_cast<const ull*>(&fp[j * 32]);
                ull ad;
                DUP32(ad, __float_as_uint(cr[j]));
                FMA2(accz, ad, b2);
            }
            spartU[tid] = accz;
            __syncthreads();

            float lp = 0.f, es = 0.f;
            if (tid < 128) {
                float z0 = 0.f, z1 = 0.f;
#pragma unroll
                for (int p = 0; p < 4; p++) {
                    float lo, hi;
                    UNPACK2(lo, hi, spartU[tid + p * 128]);
                    z0 += lo; z1 += hi;
                }
                int f = cg * 32 + f2 * 2;
                int r = rows8 + rloc;
                size_t base = ((size_t)r * Tsz + t) * Fsz + f;
                float zz[2] = { z0 + feat_b[f], z1 + feat_b[f + 1] };
#pragma unroll
                for (int c = 0; c < 2; c++) {
                    float xh = g_xhist[r * Fsz + f + c];
                    float a = g_alpha[base + c];
                    float mv = m[base + c], xv = x[base + c];
                    float ch = a * zz[c] + (1.f - a) * xh;
                    float cc = mv * xv + (1.f - mv) * ch;
                    g_xvec[r * KC + f + c] = cc;
                    g_xvec[r * KC + (Fsz + Hsz) + f + c] = mv;
                    out[base + c] = cc;
                    float ev = target_mask[base + c];
                    float tg = target_x[base + c];
                    float d1 = xh - tg, d2 = zz[c] - tg, d3 = ch - tg;
                    lp += ev * (d1 * d1 + d2 * d2 + d3 * d3);
                    es += ev;
                }
            }
            for (int o = 16; o; o >>= 1) {
                lp += __shfl_down_sync(0xffffffffu, lp, o);
                es += __shfl_down_sync(0xffffffffu, es, o);
            }
            if ((tid & 31) == 0) { sred[tid >> 5] = lp; sred2[tid >> 5] = es; }
            __syncthreads();
            if (tid == 0) {
                float tot = 0.f, tot2 = 0.f;
                for (int i = 0; i < 16; i++) { tot += sred[i]; tot2 += sred2[i]; }
                g_losspart[t * 128 + bid] = tot;
                g_maskpart[t * 128 + bid] = tot2;
            }
            __threadfence();
            __syncthreads();
            if (tid == 0) atomicAdd(&g_fa2[r8], 1);
        }

        // ===== P4: gate GEMM 128x128x192 split-K, B resident, micro 4x8 =====
        {
            // wait for xvec of the 16 row-groups this tile reads
            if (tid < 16) {
                while (*(volatile int*)&g_fa2[(b0B >> 3) + tid] < 4 * (t + 1)) { }
            }
            __syncthreads();
            if (tid == 0) __threadfence();
            __syncthreads();

            ull acc[4][4];
#pragma unroll
            for (int i = 0; i < 4; i++)
#pragma unroll
                for (int j = 0; j < 4; j++) acc[i][j] = 0ull;

            float4 pa[2];
#pragma unroll
            for (int q = 0; q < 2; q++) {
                int i = tid + q * NTHR;
                int mm = i >> 3, kq = i & 7;
                pa[q] = *reinterpret_cast<const float4*>(
                    &g_xvec[(b0B + mm) * KC + k0b + kq * 4]);
            }

#pragma unroll 1
            for (int kb = 0; kb < 6; kb++) {
                float* sAc = sA + (kb & 1) * 4608;
#pragma unroll
                for (int q = 0; q < 2; q++) {
                    int i = tid + q * NTHR;
                    int mm = i >> 3, kq = i & 7;
                    *reinterpret_cast<float4*>(&sAc[mm * 36 + kq * 4]) = pa[q];
                }
                __syncthreads();
                if (kb < 5) {
                    const int k0n = k0b + (kb + 1) * 32;
#pragma unroll
                    for (int q = 0; q < 2; q++) {
                        int i = tid + q * NTHR;
                        int mm = i >> 3, kq = i & 7;
                        pa[q] = *reinterpret_cast<const float4*>(
                            &g_xvec[(b0B + mm) * KC + k0n + kq * 4]);
                    }
                }
                const float* sBk = sBres + kb * 32 * 128;
#pragma unroll 8
                for (int k = 0; k < 32; k++) {
                    ulonglong2 bb0 = *reinterpret_cast<const ulonglong2*>(
                        &sBk[k * 128 + tx4 * 8]);
                    ulonglong2 bb1 = *reinterpret_cast<const ulonglong2*>(
                        &sBk[k * 128 + tx4 * 8 + 4]);
#pragma unroll
                    for (int r2 = 0; r2 < 4; r2++) {
                        ull ad;
                        DUP32(ad, __float_as_uint(sAc[(ty4 * 4 + r2) * 36 + k]));
                        FMA2(acc[r2][0], ad, bb0.x);
                        FMA2(acc[r2][1], ad, bb0.y);
                        FMA2(acc[r2][2], ad, bb1.x);
                        FMA2(acc[r2][3], ad, bb1.y);
                    }
                }
            }

            // store partials
            size_t pbase = (size_t)(tile4 * 4 + ks4) * 16384;
#pragma unroll
            for (int r2 = 0; r2 < 4; r2++) {
#pragma unroll
                for (int cp = 0; cp < 4; cp++) {
                    size_t off = pbase + (size_t)(ty4 * 4 + r2) * 128 + tx4 * 8 + cp * 2;
                    *reinterpret_cast<ull*>(&g_part[off]) = acc[r2][cp];
                }
            }
            __threadfence();
            __syncthreads();
            if (tid == 0) {
                atomicAdd(&g_tilecnt[tile4], 1);
                while (*(volatile int*)&g_tilecnt[tile4] - 4 * (t + 1) < 0) { }
            }
            __syncthreads();
            __threadfence();   // acquire

            // even epilogue: each K-block handles its 32-row quarter of the tile
            size_t tb = (size_t)tile4 * 4 * 16384;
            float4 bc = *reinterpret_cast<const float4*>(&g_bcomb[n0_4 + (tid & 31) * 4]);
#pragma unroll
            for (int q = 0; q < 2; q++) {
                int idx = tid + q * NTHR;        // 0..1023 f4-cells
                int row = ks4 * 32 + (idx >> 5), u = idx & 31;
                size_t go_off = (size_t)row * 128 + u * 4;
                float4 p0 = *reinterpret_cast<const float4*>(&g_part[tb + go_off]);
                float4 p1 = *reinterpret_cast<const float4*>(&g_part[tb + 16384 + go_off]);
                float4 p2 = *reinterpret_cast<const float4*>(&g_part[tb + 32768 + go_off]);
                float4 p3 = *reinterpret_cast<const float4*>(&g_part[tb + 49152 + go_off]);
                float gi = ((p0.x + p1.x) + (p2.x + p3.x)) + bc.x;
                float gf = ((p0.y + p1.y) + (p2.y + p3.y)) + bc.y;
                float gg = ((p0.z + p1.z) + (p2.z + p3.z)) + bc.z;
                float gO = ((p0.w + p1.w) + (p2.w + p3.w)) + bc.w;
                float si = sigap(gi);
                float sf = sigap(gf);
                float so = sigap(gO);
                float tg = tanhap(gg);
                int b = b0B + row;
                int j = (n0_4 >> 2) + u;
                float cn = sf * g_c[b * Hsz + j] + si * tg;
                g_c[b * Hsz + j] = cn;
                g_h[b * Hsz + j] = so * tanhap(cn);
            }
            __threadfence();
            __syncthreads();
            if (tid == 0) atomicAdd(&g_fh[(b0B >> 5) + ks4], 1);
        }
    }
}

// ----------------------------------------------------------------------
__global__ void loss_final(float* __restrict__ out, int out_size) {
    __shared__ float s[128];
    int t = threadIdx.x;
    float v = 0.f, mv = 0.f;
    for (int p = 0; p < 128; p++) {
        v += g_losspart[t * 128 + p];
        mv += g_maskpart[t * 128 + p];
    }
    s[t] = v / (mv + 1e-8f);
    __syncthreads();
    if (t == 0) {
        float tot = 0.f;
        for (int i = 0; i < 128; i++) tot += s[i];
        out[out_size - 1] = tot / (float)Tsz;
    }
}

// ----------------------------------------------------------------------
extern "C" void kernel_launch(void* const* d_in, const int* in_sizes, int n_in,
                              void* d_out, int out_size) {
    const float* x           = (const float*)d_in[0];
    const float* m           = (const float*)d_in[1];
    const float* d           = (const float*)d_in[2];
    const float* target_x    = (const float*)d_in[3];
    const float* target_mask = (const float*)d_in[4];
    const float* td_h_W      = (const float*)d_in[5];
    const float* td_h_b      = (const float*)d_in[6];
    const float* td_x_W      = (const float*)d_in[7];
    const float* td_x_b      = (const float*)d_in[8];
    const float* hist_W      = (const float*)d_in[9];
    const float* hist_b      = (const float*)d_in[10];
    const float* feat_W      = (const float*)d_in[11];
    const float* feat_b      = (const float*)d_in[12];
    const float* wc_W        = (const float*)d_in[13];
    const float* wc_b        = (const float*)d_in[14];
    const float* W_ih        = (const float*)d_in[15];
    const float* W_hh        = (const float*)d_in[16];
    const float* b_ih        = (const float*)d_in[17];
    const float* b_hh        = (const float*)d_in[18];
    float* out = (float*)d_out;

    cudaFuncSetAttribute(rits_persistent,
                         cudaFuncAttributeMaxDynamicSharedMemorySize, SMEM_BYTES);

    prep_weights<<<512, 256>>>(td_h_W, hist_W, feat_W, wc_W, W_ih, W_hh, b_ih, b_hh);
    gammah_gemm<<<dim3(BT / 64, Hsz / 64), 256>>>(d, td_h_b);
    alpha_gemm<<<dim3(BT / 64, Fsz / 64), 256>>>(d, m, td_x_W, td_x_b, wc_b);

    rits_persistent<<<NBLK, NTHR, SMEM_BYTES>>>(x, m, target_x, target_mask,
                                                hist_b, feat_b, out);

    loss_final<<<1, 128>>>(out, out_size);
}

// round 15
// speedup vs baseline: 1.7712x; 1.4146x over previous
#include <cuda_runtime.h>
#include <math.h>
#include <stdint.h>

#define Bsz 256
#define Tsz 128
#define Fsz 128
#define Hsz 512
#define BT  (Bsz * Tsz)          // 32768
#define KC  768                  // c_c(128) + h_dec(512) + m(128)
#define N4H 2048                 // 4*H, gate-interleaved
#define NBLK 128                 // persistent grid size
#define NTHR 512

typedef unsigned long long ull;

// ----- device scratch (allocation-free rule: __device__ globals) -----
__device__ __align__(16) float g_h[Bsz * Hsz];
__device__ __align__(16) float g_c[Bsz * Hsz];
__device__ __align__(16) float g_xvec[Bsz * KC];
__device__ __align__(16) float g_xhist[Bsz * Fsz];
__device__ __align__(16) float g_gamma_h[(size_t)BT * Hsz];   // 64 MB
__device__ __align__(16) float g_alpha[BT * Fsz];
__device__ float g_losspart[Tsz * 128];
__device__ float g_maskpart[Tsz * 128];
__device__ __align__(16) float g_tdhT[Fsz * Hsz];
__device__ __align__(16) float g_histT[Hsz * Fsz];            // [k][f]
__device__ __align__(16) float g_featMT[Fsz * Fsz];           // [j][f]
__device__ __align__(16) float g_wcT[2 * Fsz * Fsz];
__device__ __align__(16) float g_WcombT[KC * N4H];
__device__ __align__(16) float g_bcomb[N4H];
__device__ __align__(16) float g_part[(size_t)32 * 4 * 128 * 128];  // P4 split-K partials

// dataflow counters (monotone within a replay; reset in init)
__device__ int g_fxh[32];      // A1 arrivals per 8-row group (target 4(t+1))
__device__ int g_fa2[32];      // A2 arrivals per 8-row group (target 4(t+1))
__device__ int g_fh[8];        // P4 epilogue arrivals per 32-row h group (target 16(t+1))
__device__ int g_tilecnt[32];  // P4 per-tile K-split gate (target 4(t+1))

// flag-array grid barrier (init only)
__device__ volatile int g_arrive[NBLK];
__device__ volatile int g_release;

__device__ __forceinline__ float fsigmoid(float v) {
    return __fdividef(1.f, 1.f + __expf(-v));
}
__device__ __forceinline__ float tanhap(float x) {
    float r;
    asm("tanh.approx.f32 %0, %1;" : "=f"(r) : "f"(x));
    return r;
}
__device__ __forceinline__ float sigap(float v) {
    return 0.5f * tanhap(0.5f * v) + 0.5f;
}

// ---------------- tf32 mma.sync helpers (baseline sm_80 PTX; no 'a' features) ----------------
__device__ __forceinline__ uint32_t tf32_hi(float v) {
    uint32_t r;
    asm("cvt.rna.tf32.f32 %0, %1;" : "=r"(r) : "f"(v));
    return r;
}
__device__ __forceinline__ uint32_t tf32_lo(float v, uint32_t hi) {
    float rem = v - __uint_as_float(hi);
    uint32_t r;
    asm("cvt.rna.tf32.f32 %0, %1;" : "=r"(r) : "f"(rem));
    return r;
}
#define MMA8(c, a, b0, b1) \
    asm volatile("mma.sync.aligned.m16n8k8.row.col.f32.tf32.tf32.f32 " \
        "{%0,%1,%2,%3}, {%4,%5,%6,%7}, {%8,%9}, {%0,%1,%2,%3};" \
        : "+f"((c)[0]), "+f"((c)[1]), "+f"((c)[2]), "+f"((c)[3]) \
        : "r"((a)[0]), "r"((a)[1]), "r"((a)[2]), "r"((a)[3]), "r"(b0), "r"(b1))

// ----------------------------------------------------------------------
__global__ void prep_weights(const float* __restrict__ td_h_W,
                             const float* __restrict__ hist_W,
                             const float* __restrict__ feat_W,
                             const float* __restrict__ wc_W,
                             const float* __restrict__ W_ih,
                             const float* __restrict__ W_hh,
                             const float* __restrict__ b_ih,
                             const float* __restrict__ b_hh) {
    int stride = gridDim.x * blockDim.x;
    int tid = blockIdx.x * blockDim.x + threadIdx.x;
    for (int i = tid; i < Fsz * Hsz; i += stride) {
        int k = i / Hsz, n = i % Hsz;
        g_tdhT[i] = td_h_W[n * Fsz + k];
    }
    for (int i = tid; i < Hsz * Fsz; i += stride) {
        int k = i / Fsz, f = i % Fsz;
        g_histT[i] = hist_W[f * Hsz + k];
    }
    for (int i = tid; i < Fsz * Fsz; i += stride) {
        int j = i / Fsz, f = i % Fsz;
        g_featMT[i] = (j == f) ? 0.f : feat_W[f * Fsz + j];
    }
    for (int i = tid; i < 2 * Fsz * Fsz; i += stride) {
        int k = i / Fsz, n = i % Fsz;
        g_wcT[i] = wc_W[n * 2 * Fsz + k];
    }
    for (int i = tid; i < KC * N4H; i += stride) {
        int k = i / N4H, n = i % N4H;
        int j = n >> 2, g = n & 3;
        int row = g * Hsz + j;
        float v;
        if (k < Fsz)            v = W_ih[row * (2 * Fsz) + k];
        else if (k < Fsz + Hsz) v = W_hh[row * Hsz + (k - Fsz)];
        else                    v = W_ih[row * (2 * Fsz) + Fsz + (k - Fsz - Hsz)];
        g_WcombT[i] = v;
    }
    for (int i = tid; i < N4H; i += stride) {
        int j = i >> 2, g = i & 3;
        g_bcomb[i] = b_ih[g * Hsz + j] + b_hh[g * Hsz + j];
    }
}

// ----------------------------------------------------------------------
__global__ void gammah_gemm(const float* __restrict__ d,
                            const float* __restrict__ td_h_b) {
    __shared__ float sA[64][33];
    __shared__ float sB[32][64];
    int m0 = blockIdx.x * 64;
    int n0 = blockIdx.y * 64;
    int tid = threadIdx.x;
    int tx = tid & 15, ty = tid >> 4;
    float acc[4][4] = {};
    for (int kk = 0; kk < Fsz; kk += 32) {
        for (int i = tid; i < 64 * 32; i += 256) {
            int r = i >> 5, k = i & 31;
            sA[r][k] = d[(size_t)(m0 + r) * Fsz + kk + k];
        }
        for (int i = tid; i < 32 * 64; i += 256) {
            int k = i >> 6, n = i & 63;
            sB[k][n] = g_tdhT[(kk + k) * Hsz + n0 + n];
        }
        __syncthreads();
#pragma unroll
        for (int k = 0; k < 32; k++) {
            float a[4], b[4];
#pragma unroll
            for (int i = 0; i < 4; i++) a[i] = sA[ty + i * 16][k];
#pragma unroll
            for (int j = 0; j < 4; j++) b[j] = sB[k][tx + j * 16];
#pragma unroll
            for (int i = 0; i < 4; i++)
#pragma unroll
                for (int j = 0; j < 4; j++) acc[i][j] += a[i] * b[j];
        }
        __syncthreads();
    }
#pragma unroll
    for (int i = 0; i < 4; i++)
#pragma unroll
        for (int j = 0; j < 4; j++) {
            int n = n0 + tx + j * 16;
            int row = m0 + ty + i * 16;
            g_gamma_h[(size_t)row * Hsz + n] = __expf(-fmaxf(acc[i][j] + td_h_b[n], 0.f));
        }
}

// ----------------------------------------------------------------------
__global__ void alpha_gemm(const float* __restrict__ d,
                           const float* __restrict__ m,
                           const float* __restrict__ td_x_W,
                           const float* __restrict__ td_x_b,
                           const float* __restrict__ wc_b) {
    __shared__ float sA[64][33];
    __shared__ float sB[32][64];
    int m0 = blockIdx.x * 64;
    int n0 = blockIdx.y * 64;
    int tid = threadIdx.x;
    int tx = tid & 15, ty = tid >> 4;
    float acc[4][4] = {};
    for (int kk = 0; kk < 2 * Fsz; kk += 32) {
        for (int i = tid; i < 64 * 32; i += 256) {
            int r = i >> 5, k = i & 31;
            int kg = kk + k;
            float v;
            if (kg < Fsz) {
                float dv = d[(size_t)(m0 + r) * Fsz + kg];
                float u = dv * td_x_W[kg * Fsz + kg] + td_x_b[kg];
                v = __expf(-fmaxf(u, 0.f));
            } else {
                v = m[(size_t)(m0 + r) * Fsz + (kg - Fsz)];
            }
            sA[r][k] = v;
        }
        for (int i = tid; i < 32 * 64; i += 256) {
            int k = i >> 6, n = i & 63;
            sB[k][n] = g_wcT[(kk + k) * Fsz + n0 + n];
        }
        __syncthreads();
#pragma unroll
        for (int k = 0; k < 32; k++) {
            float a[4], b[4];
#pragma unroll
            for (int i = 0; i < 4; i++) a[i] = sA[ty + i * 16][k];
#pragma unroll
            for (int j = 0; j < 4; j++) b[j] = sB[k][tx + j * 16];
#pragma unroll
            for (int i = 0; i < 4; i++)
#pragma unroll
                for (int j = 0; j < 4; j++) acc[i][j] += a[i] * b[j];
        }
        __syncthreads();
    }
#pragma unroll
    for (int i = 0; i < 4; i++)
#pragma unroll
        for (int j = 0; j < 4; j++) {
            int n = n0 + tx + j * 16;
            int row = m0 + ty + i * 16;
            float v = acc[i][j] + wc_b[n];
            g_alpha[row * Fsz + n] = fsigmoid(v);
        }
}

// ======================================================================
#define FMA2(acc, a2, b2) \
    asm("fma.rn.f32x2 %0, %1, %2, %0;" : "+l"(acc) : "l"(a2), "l"(b2))
#define DUP32(d, s) \
    asm("mov.b64 %0, {%1, %1};" : "=l"(d) : "r"(s))
#define UNPACK2(lo, hi, in) \
    asm("mov.b64 {%0, %1}, %2;" : "=f"(lo), "=f"(hi) : "l"(in))

// flag-array barrier (init only)
__device__ __forceinline__ void grid_sync(int& gen) {
    gen++;
    __threadfence();
    __syncthreads();
    if (blockIdx.x == 0) {
        int tid = threadIdx.x;
        if (tid > 0 && tid < NBLK) {
            while (g_arrive[tid] - gen < 0) { }
        }
        __syncthreads();
        if (tid == 0) g_release = gen;
    } else {
        if (threadIdx.x == 0) {
            g_arrive[blockIdx.x] = gen;
            while (g_release - gen < 0) { }
        }
    }
    __syncthreads();
    __threadfence();
}

// dynamic smem layout (floats):
//  [0, 26112)          sBres  [192][136]  P4 B tile (k-major, pad 136), resident
//  [26112, 42496)      sHist  [512][32]   histT col-slice, resident
//  [42496, 46592)      sFeat  [128][32]   featMT col-slice, resident
//  [46592, 55808)      working:
//     P4: sA double buffer 2 x [128][36] = 9216
//     A:  sh[8][512]=4096 | sxc[8][132]=1056 @+4096 | spartU ull[512] @+5152(f)
//         sred[16] @+6176 | sred2[16] @+6192
#define OFF_HIST 26112
#define OFF_FEAT 42496
#define OFF_WORK 46592
#define SMEM_FLOATS 55808
#define SMEM_BYTES (SMEM_FLOATS * 4)

__global__ void __launch_bounds__(NTHR, 1)
rits_persistent(const float* __restrict__ x,
                const float* __restrict__ m,
                const float* __restrict__ target_x,
                const float* __restrict__ target_mask,
                const float* __restrict__ hist_b,
                const float* __restrict__ feat_b,
                float* __restrict__ out) {
    extern __shared__ __align__(16) float smem[];
    float* sBres = smem;
    float* sHist = smem + OFF_HIST;
    float* sFeat = smem + OFF_FEAT;
    float* sA    = smem + OFF_WORK;          // 2 x [128][36]
    float* sh    = smem + OFF_WORK;          // [8][512]
    float* sxc   = smem + OFF_WORK + 4096;   // [8][132]
    ull*   spartU = reinterpret_cast<ull*>(smem + OFF_WORK + 5152);  // [512]
    float* sred  = smem + OFF_WORK + 6176;
    float* sred2 = smem + OFF_WORK + 6192;

    const int tid = threadIdx.x;
    const int bid = blockIdx.x;

    int gen = g_release;

    // init state + reset all dataflow counters each replay
    for (int i = bid * NTHR + tid; i < Bsz * Hsz; i += NBLK * NTHR) {
        g_h[i] = 0.f; g_c[i] = 0.f;
    }
    if (bid == 0 && tid < 32) {
        g_fxh[tid] = 0;
        g_fa2[tid] = 0;
        g_tilecnt[tid] = 0;
        if (tid < 8) g_fh[tid] = 0;
    }

    // phase A decode: block = (row-group r8 of 8 rows) x (col-group cg of 32 cols)
    const int r8 = bid >> 2, cg = bid & 3;
    const int rows8 = r8 * 8;
    const int f2 = tid & 15;
    const int rloc = (tid >> 4) & 7;
    const int ksA = tid >> 7;

    // P4 decode: 32 tiles (2 row x 16 col of 128x128) x 4-way K-split (192)
    const int ks4  = bid & 3;
    const int tile4 = bid >> 2;
    const int b0B = (tile4 >> 4) * 128;
    const int n0_4 = (tile4 & 15) * 128;
    const int k0b = ks4 * 192;

    // P4 mma decode: 16 warps, warp tile 32x32
    const int warp = tid >> 5, lane = tid & 31;
    const int m0w = (warp & 3) * 32, n0w = (warp >> 2) * 32;
    const int qr = lane >> 2, ql = lane & 3;

    // -------- load resident weights once --------
    for (int idx = tid; idx < 192 * 128; idx += NTHR) {      // sBres [k][n] stride 136
        int k = idx >> 7, n = idx & 127;
        sBres[k * 136 + n] = g_WcombT[(size_t)(k0b + k) * N4H + n0_4 + n];
    }
#pragma unroll
    for (int q = 0; q < 8; q++) {           // sHist: 4096 f4
        int idx = tid + q * NTHR;
        int k = idx >> 3, fq = idx & 7;
        *reinterpret_cast<float4*>(&sHist[k * 32 + fq * 4]) =
            *reinterpret_cast<const float4*>(
                &g_histT[k * Fsz + cg * 32 + fq * 4]);
    }
#pragma unroll
    for (int q = 0; q < 2; q++) {           // sFeat: 1024 f4
        int idx = tid + q * NTHR;
        int j = idx >> 3, fq = idx & 7;
        *reinterpret_cast<float4*>(&sFeat[j * 32 + fq * 4]) =
            *reinterpret_cast<const float4*>(
                &g_featMT[j * Fsz + cg * 32 + fq * 4]);
    }
    grid_sync(gen);   // counters reset + h/c zero + residents loaded

#pragma unroll 1
    for (int t = 0; t < Tsz; t++) {
        // ================= A1: x_hist col-slice GEMM (resident histT) =================
        {
            if (t > 0) {
                if (tid == 0) {
                    while (*(volatile int*)&g_fh[r8 >> 2] < 16 * t) { }
                    __threadfence();
                }
                __syncthreads();
            }

#pragma unroll
            for (int q = 0; q < 2; q++) {
                int idx = tid + q * NTHR;       // 0..1023 f4
                int r = idx >> 7, kq = idx & 127;
                const float4 h4 = *reinterpret_cast<const float4*>(
                    &g_h[(rows8 + r) * Hsz + kq * 4]);
                const float4 g4 = *reinterpret_cast<const float4*>(
                    &g_gamma_h[((size_t)(rows8 + r) * Tsz + t) * Hsz + kq * 4]);
                float4 o;
                o.x = h4.x * g4.x; o.y = h4.y * g4.y;
                o.z = h4.z * g4.z; o.w = h4.w * g4.w;
                *reinterpret_cast<float4*>(&sh[r * 512 + kq * 4]) = o;
                if (cg == 0)
                    *reinterpret_cast<float4*>(
                        &g_xvec[(rows8 + r) * KC + Fsz + kq * 4]) = o;
            }
            __syncthreads();

            ull acc = 0ull;
            const float* hr = sh + rloc * 512 + ksA * 128;
            const float* wp = sHist + ksA * 128 * 32 + f2 * 2;
#pragma unroll 8
            for (int k = 0; k < 128; k++) {
                ull b2 = *reinterpret_cast<const ull*>(&wp[k * 32]);
                ull ad;
                DUP32(ad, __float_as_uint(hr[k]));
                FMA2(acc, ad, b2);
            }
            spartU[tid] = acc;
            __syncthreads();
            if (tid < 128) {
                float s0 = 0.f, s1 = 0.f;
#pragma unroll
                for (int p = 0; p < 4; p++) {
                    float lo, hi;
                    UNPACK2(lo, hi, spartU[tid + p * 128]);
                    s0 += lo; s1 += hi;
                }
                int f = cg * 32 + f2 * 2;
                g_xhist[(rows8 + rloc) * Fsz + f]     = s0 + hist_b[f];
                g_xhist[(rows8 + rloc) * Fsz + f + 1] = s1 + hist_b[f + 1];
            }
            __threadfence();
            __syncthreads();
            if (tid == 0) atomicAdd(&g_fxh[r8], 1);
        }

        // ================= A2: z_h col-slice + elementwise + loss =================
        {
            if (tid == 0) {
                while (*(volatile int*)&g_fxh[r8] < 4 * (t + 1)) { }
                __threadfence();
            }
            __syncthreads();

            if (tid < 256) {                    // x_c: 256 f4 cells
                int r = tid >> 5, jq = tid & 31;
                size_t base = ((size_t)(rows8 + r) * Tsz + t) * Fsz + jq * 4;
                float4 mv = *reinterpret_cast<const float4*>(&m[base]);
                float4 xv = *reinterpret_cast<const float4*>(&x[base]);
                float4 xh = *reinterpret_cast<const float4*>(
                    &g_xhist[(rows8 + r) * Fsz + jq * 4]);
                float4 o;
                o.x = mv.x * xv.x + (1.f - mv.x) * xh.x;
                o.y = mv.y * xv.y + (1.f - mv.y) * xh.y;
                o.z = mv.z * xv.z + (1.f - mv.z) * xh.z;
                o.w = mv.w * xv.w + (1.f - mv.w) * xh.w;
                *reinterpret_cast<float4*>(&sxc[r * 132 + jq * 4]) = o;
            }
            __syncthreads();

            ull accz = 0ull;
            const float* cr = sxc + rloc * 132 + ksA * 32;
            const float* fp = sFeat + ksA * 32 * 32 + f2 * 2;
#pragma unroll 8
            for (int j = 0; j < 32; j++) {
                ull b2 = *reinterpret_cast<const ull*>(&fp[j * 32]);
                ull ad;
                DUP32(ad, __float_as_uint(cr[j]));
                FMA2(accz, ad, b2);
            }
            spartU[tid] = accz;
            __syncthreads();

            float lp = 0.f, es = 0.f;
            if (tid < 128) {
                float z0 = 0.f, z1 = 0.f;
#pragma unroll
                for (int p = 0; p < 4; p++) {
                    float lo, hi;
                    UNPACK2(lo, hi, spartU[tid + p * 128]);
                    z0 += lo; z1 += hi;
                }
                int f = cg * 32 + f2 * 2;
                int r = rows8 + rloc;
                size_t base = ((size_t)r * Tsz + t) * Fsz + f;
                float zz[2] = { z0 + feat_b[f], z1 + feat_b[f + 1] };
#pragma unroll
                for (int c = 0; c < 2; c++) {
                    float xh = g_xhist[r * Fsz + f + c];
                    float a = g_alpha[base + c];
                    float mv = m[base + c], xv = x[base + c];
                    float ch = a * zz[c] + (1.f - a) * xh;
                    float cc = mv * xv + (1.f - mv) * ch;
                    g_xvec[r * KC + f + c] = cc;
                    g_xvec[r * KC + (Fsz + Hsz) + f + c] = mv;
                    out[base + c] = cc;
                    float ev = target_mask[base + c];
                    float tg = target_x[base + c];
                    float d1 = xh - tg, d2 = zz[c] - tg, d3 = ch - tg;
                    lp += ev * (d1 * d1 + d2 * d2 + d3 * d3);
                    es += ev;
                }
            }
            for (int o = 16; o; o >>= 1) {
                lp += __shfl_down_sync(0xffffffffu, lp, o);
                es += __shfl_down_sync(0xffffffffu, es, o);
            }
            if ((tid & 31) == 0) { sred[tid >> 5] = lp; sred2[tid >> 5] = es; }
            __syncthreads();
            if (tid == 0) {
                float tot = 0.f, tot2 = 0.f;
                for (int i = 0; i < 16; i++) { tot += sred[i]; tot2 += sred2[i]; }
                g_losspart[t * 128 + bid] = tot;
                g_maskpart[t * 128 + bid] = tot2;
            }
            __threadfence();
            __syncthreads();
            if (tid == 0) atomicAdd(&g_fa2[r8], 1);
        }

        // ===== P4: gate GEMM 128x128x192 via mma.sync tf32 (3xTF32), B resident =====
        {
            // wait for xvec of the 16 row-groups this tile reads
            if (tid < 16) {
                while (*(volatile int*)&g_fa2[(b0B >> 3) + tid] < 4 * (t + 1)) { }
            }
            __syncthreads();
            if (tid == 0) __threadfence();
            __syncthreads();

            float acc[2][4][4];
#pragma unroll
            for (int i = 0; i < 2; i++)
#pragma unroll
                for (int j = 0; j < 4; j++)
#pragma unroll
                    for (int c = 0; c < 4; c++) acc[i][j][c] = 0.f;

            float4 pa[2];
#pragma unroll
            for (int q = 0; q < 2; q++) {
                int i = tid + q * NTHR;
                int mm = i >> 3, kq = i & 7;
                pa[q] = *reinterpret_cast<const float4*>(
                    &g_xvec[(b0B + mm) * KC + k0b + kq * 4]);
            }

#pragma unroll 1
            for (int kb = 0; kb < 6; kb++) {
                float* sAc = sA + (kb & 1) * 4608;
#pragma unroll
                for (int q = 0; q < 2; q++) {
                    int i = tid + q * NTHR;
                    int mm = i >> 3, kq = i & 7;
                    *reinterpret_cast<float4*>(&sAc[mm * 36 + kq * 4]) = pa[q];
                }
                __syncthreads();
                if (kb < 5) {
                    const int k0n = k0b + (kb + 1) * 32;
#pragma unroll
                    for (int q = 0; q < 2; q++) {
                        int i = tid + q * NTHR;
                        int mm = i >> 3, kq = i & 7;
                        pa[q] = *reinterpret_cast<const float4*>(
                            &g_xvec[(b0B + mm) * KC + k0n + kq * 4]);
                    }
                }
                const float* sBk = sBres + kb * 32 * 136;
#pragma unroll
                for (int ks = 0; ks < 4; ks++) {
                    const int kk = ks * 8;
                    uint32_t ahi[2][4], alo[2][4];
#pragma unroll
                    for (int mf = 0; mf < 2; mf++) {
                        const float* ap = sAc + (m0w + mf * 16 + qr) * 36 + kk + ql;
                        float a0 = ap[0];
                        float a1 = ap[8 * 36];
                        float a2 = ap[4];
                        float a3 = ap[8 * 36 + 4];
                        ahi[mf][0] = tf32_hi(a0); alo[mf][0] = tf32_lo(a0, ahi[mf][0]);
                        ahi[mf][1] = tf32_hi(a1); alo[mf][1] = tf32_lo(a1, ahi[mf][1]);
                        ahi[mf][2] = tf32_hi(a2); alo[mf][2] = tf32_lo(a2, ahi[mf][2]);
                        ahi[mf][3] = tf32_hi(a3); alo[mf][3] = tf32_lo(a3, ahi[mf][3]);
                    }
#pragma unroll
                    for (int nf = 0; nf < 4; nf++) {
                        const float* bp = sBk + (kk + ql) * 136 + n0w + nf * 8 + qr;
                        float b0 = bp[0];
                        float b1 = bp[4 * 136];
                        uint32_t bh0 = tf32_hi(b0), bl0 = tf32_lo(b0, bh0);
                        uint32_t bh1 = tf32_hi(b1), bl1 = tf32_lo(b1, bh1);
#pragma unroll
                        for (int mf = 0; mf < 2; mf++) {
                            MMA8(acc[mf][nf], ahi[mf], bl0, bl1);
                            MMA8(acc[mf][nf], alo[mf], bh0, bh1);
                            MMA8(acc[mf][nf], ahi[mf], bh0, bh1);
                        }
                    }
                }
            }

            // store fragment results to g_part (row-major [row][128])
            size_t pbase = (size_t)(tile4 * 4 + ks4) * 16384;
#pragma unroll
            for (int mf = 0; mf < 2; mf++) {
#pragma unroll
                for (int nf = 0; nf < 4; nf++) {
                    int row = m0w + mf * 16 + qr;
                    int col = n0w + nf * 8 + 2 * ql;
                    float2 v0 = make_float2(acc[mf][nf][0], acc[mf][nf][1]);
                    float2 v1 = make_float2(acc[mf][nf][2], acc[mf][nf][3]);
                    *reinterpret_cast<float2*>(&g_part[pbase + (size_t)row * 128 + col]) = v0;
                    *reinterpret_cast<float2*>(&g_part[pbase + (size_t)(row + 8) * 128 + col]) = v1;
                }
            }
            __threadfence();
            __syncthreads();
            if (tid == 0) {
                atomicAdd(&g_tilecnt[tile4], 1);
                while (*(volatile int*)&g_tilecnt[tile4] - 4 * (t + 1) < 0) { }
            }
            __syncthreads();
            __threadfence();   // acquire

            // even epilogue: each K-block handles its 32-row quarter of the tile
            size_t tb = (size_t)tile4 * 4 * 16384;
            float4 bc = *reinterpret_cast<const float4*>(&g_bcomb[n0_4 + (tid & 31) * 4]);
#pragma unroll
            for (int q = 0; q < 2; q++) {
                int idx = tid + q * NTHR;        // 0..1023 f4-cells
                int row = ks4 * 32 + (idx >> 5), u = idx & 31;
                size_t go_off = (size_t)row * 128 + u * 4;
                float4 p0 = *reinterpret_cast<const float4*>(&g_part[tb + go_off]);
                float4 p1 = *reinterpret_cast<const float4*>(&g_part[tb + 16384 + go_off]);
                float4 p2 = *reinterpret_cast<const float4*>(&g_part[tb + 32768 + go_off]);
                float4 p3 = *reinterpret_cast<const float4*>(&g_part[tb + 49152 + go_off]);
                float gi = ((p0.x + p1.x) + (p2.x + p3.x)) + bc.x;
                float gf = ((p0.y + p1.y) + (p2.y + p3.y)) + bc.y;
                float gg = ((p0.z + p1.z) + (p2.z + p3.z)) + bc.z;
                float gO = ((p0.w + p1.w) + (p2.w + p3.w)) + bc.w;
                float si = sigap(gi);
                float sf = sigap(gf);
                float so = sigap(gO);
                float tg = tanhap(gg);
                int b = b0B + row;
                int j = (n0_4 >> 2) + u;
                float cn = sf * g_c[b * Hsz + j] + si * tg;
                g_c[b * Hsz + j] = cn;
                g_h[b * Hsz + j] = so * tanhap(cn);
            }
            __threadfence();
            __syncthreads();
            if (tid == 0) atomicAdd(&g_fh[(b0B >> 5) + ks4], 1);
        }
    }
}

// ----------------------------------------------------------------------
__global__ void loss_final(float* __restrict__ out, int out_size) {
    __shared__ float s[128];
    int t = threadIdx.x;
    float v = 0.f, mv = 0.f;
    for (int p = 0; p < 128; p++) {
        v += g_losspart[t * 128 + p];
        mv += g_maskpart[t * 128 + p];
    }
    s[t] = v / (mv + 1e-8f);
    __syncthreads();
    if (t == 0) {
        float tot = 0.f;
        for (int i = 0; i < 128; i++) tot += s[i];
        out[out_size - 1] = tot / (float)Tsz;
    }
}

// ----------------------------------------------------------------------
extern "C" void kernel_launch(void* const* d_in, const int* in_sizes, int n_in,
                              void* d_out, int out_size) {
    const float* x           = (const float*)d_in[0];
    const float* m           = (const float*)d_in[1];
    const float* d           = (const float*)d_in[2];
    const float* target_x    = (const float*)d_in[3];
    const float* target_mask = (const float*)d_in[4];
    const float* td_h_W      = (const float*)d_in[5];
    const float* td_h_b      = (const float*)d_in[6];
    const float* td_x_W      = (const float*)d_in[7];
    const float* td_x_b      = (const float*)d_in[8];
    const float* hist_W      = (const float*)d_in[9];
    const float* hist_b      = (const float*)d_in[10];
    const float* feat_W      = (const float*)d_in[11];
    const float* feat_b      = (const float*)d_in[12];
    const float* wc_W        = (const float*)d_in[13];
    const float* wc_b        = (const float*)d_in[14];
    const float* W_ih        = (const float*)d_in[15];
    const float* W_hh        = (const float*)d_in[16];
    const float* b_ih        = (const float*)d_in[17];
    const float* b_hh        = (const float*)d_in[18];
    float* out = (float*)d_out;

    cudaFuncSetAttribute(rits_persistent,
                         cudaFuncAttributeMaxDynamicSharedMemorySize, SMEM_BYTES);

    prep_weights<<<512, 256>>>(td_h_W, hist_W, feat_W, wc_W, W_ih, W_hh, b_ih, b_hh);
    gammah_gemm<<<dim3(BT / 64, Hsz / 64), 256>>>(d, td_h_b);
    alpha_gemm<<<dim3(BT / 64, Fsz / 64), 256>>>(d, m, td_x_W, td_x_b, wc_b);

    rits_persistent<<<NBLK, NTHR, SMEM_BYTES>>>(x, m, target_x, target_mask,
                                                hist_b, feat_b, out);

    loss_final<<<1, 128>>>(out, out_size);
}